// round 1
// baseline (speedup 1.0000x reference)
#include <cuda_runtime.h>
#include <cstdint>
#include <cstddef>

// Problem constants (fixed by setup_inputs)
#define B_   2
#define S_   2048
#define H_   2048
#define NH_  32
#define NKV_ 8
#define HD_  64
#define QKVN 3072
#define BS_  (B_ * S_)   // 4096

// ---------------- scratch (device globals: allocation-free) ----------------
__device__ __align__(16) float g_qkv[(size_t)BS_ * QKVN];   // 50.3 MB
__device__ __align__(16) float g_q[(size_t)BS_ * NH_ * HD_]; // 33.5 MB (score-scale folded in)
__device__ __align__(16) float g_k[(size_t)BS_ * NKV_ * HD_];// 8.4 MB
__device__ __align__(16) float g_attn[(size_t)BS_ * NH_ * HD_]; // 33.5 MB

typedef unsigned long long u64;

// ---------------- packed f32x2 helpers (Blackwell FFMA2 path) ----------------
__device__ __forceinline__ u64 dup2(float x) {
    unsigned xi = __float_as_uint(x);
    u64 r;
    asm("mov.b64 %0, {%1, %1};" : "=l"(r) : "r"(xi));
    return r;
}
__device__ __forceinline__ void ffma2(u64& d, u64 a, u64 b) {
    asm("fma.rn.f32x2 %0, %1, %2, %0;" : "+l"(d) : "l"(a), "l"(b));
}
__device__ __forceinline__ u64 mul2(u64 a, u64 b) {
    u64 r;
    asm("mul.rn.f32x2 %0, %1, %2;" : "=l"(r) : "l"(a), "l"(b));
    return r;
}
__device__ __forceinline__ float2 unpk2(u64 v) {
    unsigned lo, hi;
    asm("mov.b64 {%0, %1}, %2;" : "=r"(lo), "=r"(hi) : "l"(v));
    return make_float2(__uint_as_float(lo), __uint_as_float(hi));
}

// ---------------- SGEMM: C[M,N] = A[M,K] @ W[N,K]^T  (both K-major) ----------
// 128x128 tile, BK=8, 256 threads, 8x8 micro-tile, f32x2 packed over N.
__global__ __launch_bounds__(256) void sgemm_nt(
    const float* __restrict__ A, const float* __restrict__ W,
    float* __restrict__ C, int M, int N, int K)
{
    __shared__ __align__(16) float As[8][128];
    __shared__ __align__(16) float Bs[8][128];

    const int tid = threadIdx.x;
    const int tx = tid & 15, ty = tid >> 4;
    const int bm = blockIdx.y * 128, bn = blockIdx.x * 128;
    const int lr = tid >> 1, lk = (tid & 1) * 4;

    const float* Ap = A + (size_t)(bm + lr) * K + lk;
    const float* Wp = W + (size_t)(bn + lr) * K + lk;

    u64 acc[8][4];
#pragma unroll
    for (int i = 0; i < 8; i++)
#pragma unroll
        for (int j = 0; j < 4; j++) acc[i][j] = 0ull;

    for (int kt = 0; kt < K; kt += 8) {
        float4 av = *(const float4*)(Ap + kt);
        float4 wv = *(const float4*)(Wp + kt);
        __syncthreads();   // previous compute done before overwrite
        As[lk + 0][lr] = av.x; As[lk + 1][lr] = av.y;
        As[lk + 2][lr] = av.z; As[lk + 3][lr] = av.w;
        Bs[lk + 0][lr] = wv.x; Bs[lk + 1][lr] = wv.y;
        Bs[lk + 2][lr] = wv.z; Bs[lk + 3][lr] = wv.w;
        __syncthreads();
#pragma unroll
        for (int kk = 0; kk < 8; kk++) {
            float4 a0 = *(const float4*)&As[kk][ty * 8];
            float4 a1 = *(const float4*)&As[kk][ty * 8 + 4];
            const u64* br = (const u64*)&Bs[kk][tx * 8];
            u64 b0 = br[0], b1 = br[1], b2 = br[2], b3 = br[3];
            u64 ad[8] = { dup2(a0.x), dup2(a0.y), dup2(a0.z), dup2(a0.w),
                          dup2(a1.x), dup2(a1.y), dup2(a1.z), dup2(a1.w) };
#pragma unroll
            for (int i = 0; i < 8; i++) {
                ffma2(acc[i][0], ad[i], b0);
                ffma2(acc[i][1], ad[i], b1);
                ffma2(acc[i][2], ad[i], b2);
                ffma2(acc[i][3], ad[i], b3);
            }
        }
    }
#pragma unroll
    for (int i = 0; i < 8; i++) {
        float2* crow = (float2*)(C + (size_t)(bm + ty * 8 + i) * N + bn + tx * 8);
#pragma unroll
        for (int j = 0; j < 4; j++) crow[j] = unpk2(acc[i][j]);
    }
}

// ---------------- fused per-head LayerNorm + partial NeoX RoPE ----------------
// One warp per head (32 lanes x 2 elems = 64 dims). 8 heads per 256-thread block.
// Folds attention score scale (1/8) into Q.
__global__ __launch_bounds__(256) void ln_rope(
    const float* __restrict__ qkv, const int* __restrict__ pos_ids,
    const float* __restrict__ qw, const float* __restrict__ kw,
    float* __restrict__ qo, float* __restrict__ ko)
{
    const int wid = threadIdx.x >> 5;
    const int lane = threadIdx.x & 31;
    const int bs = blockIdx.x / 5;
    const int head = (blockIdx.x % 5) * 8 + wid;   // 0..39 (32 Q + 8 K)

    const float* src = qkv + (size_t)bs * QKVN + head * HD_;
    float v0 = src[lane], v1 = src[lane + 32];

    float s = v0 + v1;
#pragma unroll
    for (int m = 16; m; m >>= 1) s += __shfl_xor_sync(~0u, s, m);
    const float mu = s * (1.0f / 64.0f);
    const float d0 = v0 - mu, d1 = v1 - mu;
    float vs = d0 * d0 + d1 * d1;
#pragma unroll
    for (int m = 16; m; m >>= 1) vs += __shfl_xor_sync(~0u, vs, m);
    const float inv = rsqrtf(vs * (1.0f / 64.0f) + 1e-5f);

    const float* w = (head < NH_) ? (qw + head * HD_) : (kw + (head - NH_) * HD_);
    float n0 = d0 * inv * w[lane];
    float n1 = d1 * inv * w[lane + 32];

    // partial RoPE on dims [0,16)
    const float p = (float)pos_ids[bs];
    const float partner = __shfl_xor_sync(~0u, n0, 8);
    if (lane < 16) {
        const int i = lane & 7;
        const float invf = powf(10000.0f, -(float)i * 0.125f);
        const float ang = p * invf;
        const float c = cosf(ang), sn = sinf(ang);
        n0 = (lane < 8) ? (n0 * c - partner * sn) : (n0 * c + partner * sn);
    }
    const float sc = (head < NH_) ? 0.125f : 1.0f;   // HEAD_DIM^-0.5 folded into Q
    n0 *= sc; n1 *= sc;

    if (head < NH_) {
        float* dst = qo + ((size_t)bs * NH_ + head) * HD_;
        dst[lane] = n0; dst[lane + 32] = n1;
    } else {
        float* dst = ko + ((size_t)bs * NKV_ + (head - NH_)) * HD_;
        dst[lane] = n0; dst[lane + 32] = n1;
    }
}

// ---------------- flash-style causal GQA attention, fp32 ----------------
// Block = (q-tile of 64, b*h). 256 threads, 4x4 micro-tile, online softmax.
// Q/K stored kk-major (transposed) in smem -> conflict-free f32x2 GEMM loads.
__global__ __launch_bounds__(256) void attn_kernel(
    const float* __restrict__ Q, const float* __restrict__ Kk,
    const float* __restrict__ qkv, float* __restrict__ O)
{
    extern __shared__ __align__(16) float sm[];
    float* Qt = sm;            // [64][64], Qt[kk][r]
    float* Kt = sm + 4096;     // [64][64], Kt[kk][j]
    float* Vs = sm + 8192;     // [64][64], Vs[j][c]
    float* Ps = sm + 12288;    // [64][64], Ps[r][j]

    const int qt = blockIdx.x;          // 0..31
    const int bh = blockIdx.y;          // 0..63
    const int b = bh >> 5, h = bh & 31, kh = h >> 2;
    const int tid = threadIdx.x;
    const int tx = tid & 15, ty = tid >> 4;

    // load + transpose Q tile (scale already folded in)
    {
        const int r = tid >> 2;
        const int c0 = (tid & 3) * 16;
        const float* qp = Q + ((size_t)(b * S_ + qt * 64 + r) * NH_ + h) * HD_ + c0;
#pragma unroll
        for (int l = 0; l < 4; l++) {
            float4 v = *(const float4*)(qp + l * 4);
            Qt[(c0 + l * 4 + 0) * 64 + r] = v.x;
            Qt[(c0 + l * 4 + 1) * 64 + r] = v.y;
            Qt[(c0 + l * 4 + 2) * 64 + r] = v.z;
            Qt[(c0 + l * 4 + 3) * 64 + r] = v.w;
        }
    }

    u64 acc[4][2];
    float mrow[4], lrow[4];
#pragma unroll
    for (int i = 0; i < 4; i++) {
        acc[i][0] = acc[i][1] = 0ull;
        mrow[i] = -1e30f; lrow[i] = 0.0f;
    }

    for (int kt = 0; kt <= qt; kt++) {
        // ---- load K (transposed) and V (natural) tiles ----
        const int r = tid >> 2;
        const int c0 = (tid & 3) * 16;
        const float* kp = Kk + ((size_t)(b * S_ + kt * 64 + r) * NKV_ + kh) * HD_ + c0;
        const float* vp = qkv + (size_t)(b * S_ + kt * 64 + r) * QKVN
                        + (NH_ * HD_ + NKV_ * HD_) + kh * HD_ + c0;
        float4 kv[4], vv[4];
#pragma unroll
        for (int l = 0; l < 4; l++) { kv[l] = *(const float4*)(kp + l * 4);
                                      vv[l] = *(const float4*)(vp + l * 4); }
        __syncthreads();   // prior iteration's PV finished reading Kt/Vs/Ps
#pragma unroll
        for (int l = 0; l < 4; l++) {
            Kt[(c0 + l * 4 + 0) * 64 + r] = kv[l].x;
            Kt[(c0 + l * 4 + 1) * 64 + r] = kv[l].y;
            Kt[(c0 + l * 4 + 2) * 64 + r] = kv[l].z;
            Kt[(c0 + l * 4 + 3) * 64 + r] = kv[l].w;
            *(float4*)&Vs[r * 64 + c0 + l * 4] = vv[l];
        }
        __syncthreads();

        // ---- S tile: s[i][j] = sum_kk Qt[kk][row] * Kt[kk][col] ----
        u64 s2[4][2];
#pragma unroll
        for (int i = 0; i < 4; i++) s2[i][0] = s2[i][1] = 0ull;
#pragma unroll 8
        for (int kk = 0; kk < 64; kk++) {
            float4 a4 = *(const float4*)&Qt[kk * 64 + ty * 4];
            const u64* brow = (const u64*)&Kt[kk * 64 + tx * 4];
            u64 b0 = brow[0], b1 = brow[1];
            u64 ad[4] = { dup2(a4.x), dup2(a4.y), dup2(a4.z), dup2(a4.w) };
#pragma unroll
            for (int i = 0; i < 4; i++) { ffma2(s2[i][0], ad[i], b0);
                                          ffma2(s2[i][1], ad[i], b1); }
        }

        float sv[4][4];
#pragma unroll
        for (int i = 0; i < 4; i++) {
            float2 p0 = unpk2(s2[i][0]), p1 = unpk2(s2[i][1]);
            sv[i][0] = p0.x; sv[i][1] = p0.y; sv[i][2] = p1.x; sv[i][3] = p1.y;
        }
        // causal mask on the diagonal tile
        if (kt == qt) {
            const int row0 = ty * 4, col0 = tx * 4;
#pragma unroll
            for (int i = 0; i < 4; i++)
#pragma unroll
                for (int j = 0; j < 4; j++)
                    if (col0 + j > row0 + i) sv[i][j] = -1e30f;
        }

        // ---- online softmax (row chunks reduced across 16 tx lanes) ----
#pragma unroll
        for (int i = 0; i < 4; i++) {
            float m = fmaxf(fmaxf(sv[i][0], sv[i][1]), fmaxf(sv[i][2], sv[i][3]));
#pragma unroll
            for (int msk = 1; msk < 16; msk <<= 1)
                m = fmaxf(m, __shfl_xor_sync(~0u, m, msk));
            const float mnew = fmaxf(mrow[i], m);
            const float alpha = __expf(mrow[i] - mnew);
            mrow[i] = mnew;
            float ps = 0.0f;
#pragma unroll
            for (int j = 0; j < 4; j++) { sv[i][j] = __expf(sv[i][j] - mnew); ps += sv[i][j]; }
#pragma unroll
            for (int msk = 1; msk < 16; msk <<= 1)
                ps += __shfl_xor_sync(~0u, ps, msk);
            lrow[i] = lrow[i] * alpha + ps;
            const u64 al = dup2(alpha);
            acc[i][0] = mul2(acc[i][0], al);
            acc[i][1] = mul2(acc[i][1], al);
            *(float4*)&Ps[(ty * 4 + i) * 64 + tx * 4] =
                make_float4(sv[i][0], sv[i][1], sv[i][2], sv[i][3]);
        }
        __syncthreads();

        // ---- O += P @ V ----
#pragma unroll 8
        for (int jj = 0; jj < 64; jj++) {
            const u64* vr = (const u64*)&Vs[jj * 64 + tx * 4];
            u64 b0 = vr[0], b1 = vr[1];
#pragma unroll
            for (int i = 0; i < 4; i++) {
                u64 pa = dup2(Ps[(ty * 4 + i) * 64 + jj]);
                ffma2(acc[i][0], pa, b0);
                ffma2(acc[i][1], pa, b1);
            }
        }
    }

    // ---- epilogue: normalize, write [b, q, h, d] ----
#pragma unroll
    for (int i = 0; i < 4; i++) {
        const float linv = 1.0f / lrow[i];
        float2 o0 = unpk2(acc[i][0]), o1 = unpk2(acc[i][1]);
        float* op = O + ((size_t)(b * S_ + qt * 64 + ty * 4 + i) * NH_ + h) * HD_ + tx * 4;
        *(float4*)op = make_float4(o0.x * linv, o0.y * linv, o1.x * linv, o1.y * linv);
    }
}

// ---------------- launch ----------------
extern "C" void kernel_launch(void* const* d_in, const int* in_sizes, int n_in,
                              void* d_out, int out_size)
{
    const int*   pos  = (const int*)d_in[0];
    const float* hid  = (const float*)d_in[1];
    const float* wqkv = (const float*)d_in[2];
    const float* qw   = (const float*)d_in[3];
    const float* kw   = (const float*)d_in[4];
    const float* wo   = (const float*)d_in[5];
    float* out = (float*)d_out;

    float *qkv, *q, *k, *attnb;
    cudaGetSymbolAddress((void**)&qkv,   g_qkv);
    cudaGetSymbolAddress((void**)&q,     g_q);
    cudaGetSymbolAddress((void**)&k,     g_k);
    cudaGetSymbolAddress((void**)&attnb, g_attn);

    cudaFuncSetAttribute(attn_kernel,
                         cudaFuncAttributeMaxDynamicSharedMemorySize, 65536);

    // 1) qkv = hidden @ w_qkv^T
    dim3 g1(QKVN / 128, BS_ / 128);
    sgemm_nt<<<g1, 256>>>(hid, wqkv, qkv, BS_, QKVN, H_);

    // 2) per-head LN + partial RoPE (+ fold score scale into Q)
    ln_rope<<<BS_ * 5, 256>>>(qkv, pos, qw, kw, q, k);

    // 3) causal GQA attention
    attn_kernel<<<dim3(S_ / 64, B_ * NH_), 256, 65536>>>(q, k, qkv, attnb);

    // 4) out = attn @ w_o^T
    dim3 g2(H_ / 128, BS_ / 128);
    sgemm_nt<<<g2, 256>>>(attnb, wo, out, BS_, H_, H_);
}

// round 4
// speedup vs baseline: 2.6738x; 2.6738x over previous
#include <cuda_runtime.h>
#include <cstdint>
#include <cstddef>

// Problem constants (fixed by setup_inputs)
#define B_   2
#define S_   2048
#define H_   2048
#define NH_  32
#define NKV_ 8
#define HD_  64
#define QKVN 3072
#define BS_  (B_ * S_)   // 4096

// ---------------- scratch (device globals: allocation-free) ----------------
__device__ __align__(16) float g_qkv[(size_t)BS_ * QKVN];
__device__ __align__(16) float g_q[(size_t)BS_ * NH_ * HD_];
__device__ __align__(16) float g_k[(size_t)BS_ * NKV_ * HD_];
__device__ __align__(16) float g_attn[(size_t)BS_ * NH_ * HD_];

// ---------------- helpers ----------------
__device__ __forceinline__ uint32_t smem_u32(const void* p) {
    uint32_t a;
    asm("{ .reg .u64 t; cvta.to.shared.u64 t, %1; cvt.u32.u64 %0, t; }" : "=r"(a) : "l"(p));
    return a;
}
__device__ __forceinline__ uint32_t tf32r(float f) {
    uint32_t r;
    asm("cvt.rna.tf32.f32 %0, %1;" : "=r"(r) : "f"(f));
    return r;
}
// m16n8k8 tf32 mma, fp32 accumulate (row.col)
__device__ __forceinline__ void mma8(float* d, const unsigned* a, unsigned b0, unsigned b1) {
    asm volatile(
        "mma.sync.aligned.m16n8k8.row.col.f32.tf32.tf32.f32 "
        "{%0,%1,%2,%3}, {%4,%5,%6,%7}, {%8,%9}, {%0,%1,%2,%3};"
        : "+f"(d[0]), "+f"(d[1]), "+f"(d[2]), "+f"(d[3])
        : "r"(a[0]), "r"(a[1]), "r"(a[2]), "r"(a[3]), "r"(b0), "r"(b1));
}
__device__ __forceinline__ void ldsm4(unsigned* r, uint32_t addr) {
    asm volatile("ldmatrix.sync.aligned.m8n8.x4.shared.b16 {%0,%1,%2,%3}, [%4];"
                 : "=r"(r[0]), "=r"(r[1]), "=r"(r[2]), "=r"(r[3]) : "r"(addr));
}

// ======================= tf32 mma GEMM: C = A[M,K] @ W[N,K]^T ===============
// 128x128 tile, BK=16, 256 threads (8 warps in 2x4), double-buffered smem.
// Smem rows of 16 floats (4 x 16B chunks), chunk swizzle: c ^= (row>>1)&3.
__device__ __forceinline__ uint32_t gaddrA(uint32_t base, int m0, int ks, int lane) {
    int sub = lane >> 3;
    int row = m0 + (sub & 1) * 8 + (lane & 7);
    int kc  = 2 * ks + (sub >> 1);
    return base + (uint32_t)(row * 16 + ((kc ^ ((row >> 1) & 3)) << 2)) * 4u;
}
__device__ __forceinline__ uint32_t gaddrB(uint32_t base, int n0, int ks, int lane) {
    int sub = lane >> 3;
    int row = n0 + (sub >> 1) * 8 + (lane & 7);
    int kc  = 2 * ks + (sub & 1);
    return base + (uint32_t)(row * 16 + ((kc ^ ((row >> 1) & 3)) << 2)) * 4u;
}
__device__ __forceinline__ void stcvt(unsigned* buf, unsigned off, float4 v) {
    uint4 u = make_uint4(tf32r(v.x), tf32r(v.y), tf32r(v.z), tf32r(v.w));
    *(uint4*)(buf + off) = u;
}

__global__ __launch_bounds__(256) void gemm_mma(
    const float* __restrict__ A, const float* __restrict__ W,
    float* __restrict__ C, int M, int N, int K)
{
    __shared__ __align__(16) unsigned As[2][2048];
    __shared__ __align__(16) unsigned Bs[2][2048];
    const int tid = threadIdx.x, lane = tid & 31, wid = tid >> 5;
    const int bm = blockIdx.y * 128, bn = blockIdx.x * 128;
    const int wm = (wid & 1) * 64, wn = (wid >> 1) * 32;

    const int tr = tid >> 1;             // 0..127
    const int tc = (tid & 1) * 2;        // chunk base
    const float* Ap = A + (size_t)(bm + tr) * K + tc * 4;
    const float* Wp = W + (size_t)(bn + tr) * K + tc * 4;
    const unsigned so0 = tr * 16 + (((tc    ) ^ ((tr >> 1) & 3)) << 2);
    const unsigned so1 = tr * 16 + (((tc + 1) ^ ((tr >> 1) & 3)) << 2);

    const uint32_t asb[2] = { smem_u32(As[0]), smem_u32(As[1]) };
    const uint32_t bsb[2] = { smem_u32(Bs[0]), smem_u32(Bs[1]) };

    float acc[16][4];
#pragma unroll
    for (int i = 0; i < 16; i++)
#pragma unroll
        for (int j = 0; j < 4; j++) acc[i][j] = 0.0f;

    // prologue: tile 0
    float4 a0 = *(const float4*)Ap,       a1 = *(const float4*)(Ap + 4);
    float4 w0 = *(const float4*)Wp,       w1 = *(const float4*)(Wp + 4);
    stcvt(As[0], so0, a0); stcvt(As[0], so1, a1);
    stcvt(Bs[0], so0, w0); stcvt(Bs[0], so1, w1);

    const int T = K >> 4;
    for (int t = 0; t < T; t++) {
        __syncthreads();
        if (t + 1 < T) {
            const float* ap = Ap + (t + 1) * 16;
            const float* wp = Wp + (t + 1) * 16;
            a0 = *(const float4*)ap; a1 = *(const float4*)(ap + 4);
            w0 = *(const float4*)wp; w1 = *(const float4*)(wp + 4);
        }
        const int buf = t & 1;
#pragma unroll
        for (int ks = 0; ks < 2; ks++) {
            unsigned af[4][4], bf[2][4];
#pragma unroll
            for (int mt = 0; mt < 4; mt++)
                ldsm4(af[mt], gaddrA(asb[buf], wm + mt * 16, ks, lane));
#pragma unroll
            for (int bp = 0; bp < 2; bp++)
                ldsm4(bf[bp], gaddrB(bsb[buf], wn + bp * 16, ks, lane));
#pragma unroll
            for (int mt = 0; mt < 4; mt++)
#pragma unroll
                for (int nt = 0; nt < 4; nt++)
                    mma8(acc[mt * 4 + nt], af[mt],
                         bf[nt >> 1][(nt & 1) * 2], bf[nt >> 1][(nt & 1) * 2 + 1]);
        }
        __syncthreads();
        if (t + 1 < T) {
            const int nb = (t + 1) & 1;
            stcvt(As[nb], so0, a0); stcvt(As[nb], so1, a1);
            stcvt(Bs[nb], so0, w0); stcvt(Bs[nb], so1, w1);
        }
    }

    // epilogue
#pragma unroll
    for (int mt = 0; mt < 4; mt++) {
        const int rA = bm + wm + mt * 16 + (lane >> 2);
        float* cA = C + (size_t)rA * N + bn + wn + (lane & 3) * 2;
        float* cB = cA + 8 * (size_t)N;
#pragma unroll
        for (int nt = 0; nt < 4; nt++) {
            *(float2*)(cA + nt * 8) = make_float2(acc[mt * 4 + nt][0], acc[mt * 4 + nt][1]);
            *(float2*)(cB + nt * 8) = make_float2(acc[mt * 4 + nt][2], acc[mt * 4 + nt][3]);
        }
    }
}

// ---------------- fused per-head LayerNorm + partial NeoX RoPE ----------------
// Outputs are tf32-rounded (rna) so attention smem fills are pure copies.
__global__ __launch_bounds__(256) void ln_rope(
    const float* __restrict__ qkv, const int* __restrict__ pos_ids,
    const float* __restrict__ qw, const float* __restrict__ kw,
    float* __restrict__ qo, float* __restrict__ ko)
{
    const int wid = threadIdx.x >> 5;
    const int lane = threadIdx.x & 31;
    const int bs = blockIdx.x / 5;
    const int head = (blockIdx.x % 5) * 8 + wid;   // 0..39 (32 Q + 8 K)

    const float* src = qkv + (size_t)bs * QKVN + head * HD_;
    float v0 = src[lane], v1 = src[lane + 32];

    float s = v0 + v1;
#pragma unroll
    for (int m = 16; m; m >>= 1) s += __shfl_xor_sync(~0u, s, m);
    const float mu = s * (1.0f / 64.0f);
    const float d0 = v0 - mu, d1 = v1 - mu;
    float vs = d0 * d0 + d1 * d1;
#pragma unroll
    for (int m = 16; m; m >>= 1) vs += __shfl_xor_sync(~0u, vs, m);
    const float inv = rsqrtf(vs * (1.0f / 64.0f) + 1e-5f);

    const float* w = (head < NH_) ? (qw + head * HD_) : (kw + (head - NH_) * HD_);
    float n0 = d0 * inv * w[lane];
    float n1 = d1 * inv * w[lane + 32];

    const float p = (float)pos_ids[bs];
    const float partner = __shfl_xor_sync(~0u, n0, 8);
    if (lane < 16) {
        const int i = lane & 7;
        const float invf = powf(10000.0f, -(float)i * 0.125f);
        const float ang = p * invf;
        const float c = cosf(ang), sn = sinf(ang);
        n0 = (lane < 8) ? (n0 * c - partner * sn) : (n0 * c + partner * sn);
    }
    const float sc = (head < NH_) ? 0.125f : 1.0f;   // HEAD_DIM^-0.5 folded into Q
    n0 = __uint_as_float(tf32r(n0 * sc));
    n1 = __uint_as_float(tf32r(n1 * sc));

    if (head < NH_) {
        float* dst = qo + ((size_t)bs * NH_ + head) * HD_;
        dst[lane] = n0; dst[lane + 32] = n1;
    } else {
        float* dst = ko + ((size_t)bs * NKV_ + (head - NH_)) * HD_;
        dst[lane] = n0; dst[lane + 32] = n1;
    }
}

// ======================= flash attention via tf32 mma =======================
// Block: 64 q-rows x (b,h). 256 threads = 8 warps: wm=(wid&3)*16 rows,
// wg=(wid>>2) column half (32 keys / 32 dims). Smem rows = 64 floats,
// chunk swizzle c ^= (row&7) (Vt adds ^((d>>4)&3) for STS conflicts).
__global__ __launch_bounds__(256, 2) void attn_mma(
    const float* __restrict__ Q, const float* __restrict__ Kg,
    const float* __restrict__ qkv, float* __restrict__ O)
{
    extern __shared__ __align__(16) char smraw[];
    float* Qs = (float*)smraw;               // [64][64] (aliased as Ps after frag preload)
    float* Ks = (float*)(smraw + 16384);
    float* Vt = (float*)(smraw + 32768);
    float* Ps = Qs;
    float* mbuf = (float*)(smraw + 49152);   // [64][2]
    float* sbuf = mbuf + 128;                // [64][2]

    const uint32_t qsb = smem_u32(Qs);
    const uint32_t ksb = smem_u32(Ks);
    const uint32_t vtb = smem_u32(Vt);

    const int qt = blockIdx.x, bh = blockIdx.y;
    const int b = bh >> 5, h = bh & 31, kh = h >> 2;
    const int tid = threadIdx.x, lane = tid & 31, wid = tid >> 5;
    const int wm = (wid & 3) * 16;
    const int wg = wid >> 2;
    const int wn = wg * 32;

    // ---- load Q tile into Qs (row-major [m][k], swizzled) ----
    {
        const int r = tid >> 2;
        const int cb = (tid & 3) * 4;   // chunk base
        const float* qp = Q + ((size_t)(b * S_ + qt * 64 + r) * NH_ + h) * HD_ + (tid & 3) * 16;
#pragma unroll
        for (int l = 0; l < 4; l++) {
            float4 v = *(const float4*)(qp + l * 4);
            *(float4*)(Qs + r * 64 + (((cb + l) ^ (r & 7)) << 2)) = v;
        }
    }
    __syncthreads();

    // ---- hoist Q A-fragments (invariant across kt) ----
    unsigned qa[8][4];
#pragma unroll
    for (int ks = 0; ks < 8; ks++) {
        const int sub = lane >> 3;
        const int row = wm + (sub & 1) * 8 + (lane & 7);
        const int kc = 2 * ks + (sub >> 1);
        ldsm4(qa[ks], qsb + (uint32_t)(row * 64 + ((kc ^ (row & 7)) << 2)) * 4u);
    }

    float acc_o[4][4];
#pragma unroll
    for (int i = 0; i < 4; i++)
#pragma unroll
        for (int j = 0; j < 4; j++) acc_o[i][j] = 0.0f;
    float mA = -1e30f, mB = -1e30f, lA = 0.0f, lB = 0.0f;

    const int rowA = wm + (lane >> 2);
    const int rowB = rowA + 8;

    for (int kt = 0; kt <= qt; kt++) {
        // ---- global loads ----
        const int r = tid >> 2;
        const int cb = (tid & 3) * 4;
        const float* kp = Kg + ((size_t)(b * S_ + kt * 64 + r) * NKV_ + kh) * HD_ + (tid & 3) * 16;
        const float* vp = qkv + (size_t)(b * S_ + kt * 64 + r) * QKVN + 2560 + kh * HD_ + (tid & 3) * 16;
        float4 kv[4], vv[4];
#pragma unroll
        for (int l = 0; l < 4; l++) { kv[l] = *(const float4*)(kp + l * 4);
                                      vv[l] = *(const float4*)(vp + l * 4); }
        __syncthreads();   // prior PV done with Ks/Vt
        // K natural [n][k] (already tf32)
#pragma unroll
        for (int l = 0; l < 4; l++)
            *(float4*)(Ks + r * 64 + (((cb + l) ^ (r & 7)) << 2)) = kv[l];
        // V transposed [d][j] with cvt
#pragma unroll
        for (int l = 0; l < 4; l++) {
            const float vals[4] = { vv[l].x, vv[l].y, vv[l].z, vv[l].w };
#pragma unroll
            for (int jj = 0; jj < 4; jj++) {
                const int d = (tid & 3) * 16 + l * 4 + jj;
                const int ch = (r >> 2) ^ (d & 7) ^ ((d >> 4) & 3);
                Vt[d * 64 + (ch << 2) + (r & 3)] = __uint_as_float(tf32r(vals[jj]));
            }
        }
        __syncthreads();

        // ---- S = Q @ K^T (warp: rows wm..+15, cols wn..+31) ----
        float sacc[4][4];
#pragma unroll
        for (int i = 0; i < 4; i++)
#pragma unroll
            for (int j = 0; j < 4; j++) sacc[i][j] = 0.0f;
#pragma unroll
        for (int ks = 0; ks < 8; ks++) {
            unsigned kb[2][4];
#pragma unroll
            for (int bp = 0; bp < 2; bp++) {
                const int sub = lane >> 3;
                const int row = wn + bp * 16 + (sub >> 1) * 8 + (lane & 7);
                const int kc = 2 * ks + (sub & 1);
                ldsm4(kb[bp], ksb + (uint32_t)(row * 64 + ((kc ^ (row & 7)) << 2)) * 4u);
            }
#pragma unroll
            for (int nt = 0; nt < 4; nt++)
                mma8(sacc[nt], qa[ks], kb[nt >> 1][(nt & 1) * 2], kb[nt >> 1][(nt & 1) * 2 + 1]);
        }

        // ---- causal mask on diagonal tile ----
        if (kt == qt) {
#pragma unroll
            for (int nt = 0; nt < 4; nt++) {
                const int c0 = wn + nt * 8 + (lane & 3) * 2;
                if (c0     > rowA) sacc[nt][0] = -1e30f;
                if (c0 + 1 > rowA) sacc[nt][1] = -1e30f;
                if (c0     > rowB) sacc[nt][2] = -1e30f;
                if (c0 + 1 > rowB) sacc[nt][3] = -1e30f;
            }
        }

        // ---- half-row max, publish ----
        float hmA = -1e30f, hmB = -1e30f;
#pragma unroll
        for (int nt = 0; nt < 4; nt++) {
            hmA = fmaxf(hmA, fmaxf(sacc[nt][0], sacc[nt][1]));
            hmB = fmaxf(hmB, fmaxf(sacc[nt][2], sacc[nt][3]));
        }
        hmA = fmaxf(hmA, __shfl_xor_sync(~0u, hmA, 1));
        hmA = fmaxf(hmA, __shfl_xor_sync(~0u, hmA, 2));
        hmB = fmaxf(hmB, __shfl_xor_sync(~0u, hmB, 1));
        hmB = fmaxf(hmB, __shfl_xor_sync(~0u, hmB, 2));
        if ((lane & 3) == 0) {
            mbuf[rowA * 2 + wg] = hmA;
            mbuf[rowB * 2 + wg] = hmB;
        }
        __syncthreads();

        const float mnA = fmaxf(mA, fmaxf(mbuf[rowA * 2], mbuf[rowA * 2 + 1]));
        const float mnB = fmaxf(mB, fmaxf(mbuf[rowB * 2], mbuf[rowB * 2 + 1]));
        const float alA = __expf(mA - mnA);
        const float alB = __expf(mB - mnB);
        mA = mnA; mB = mnB;

        // ---- exp, write Ps (tf32), half-row sums ----
        float hsA = 0.0f, hsB = 0.0f;
#pragma unroll
        for (int nt = 0; nt < 4; nt++) {
            const float p0 = __expf(sacc[nt][0] - mnA);
            const float p1 = __expf(sacc[nt][1] - mnA);
            const float p2 = __expf(sacc[nt][2] - mnB);
            const float p3 = __expf(sacc[nt][3] - mnB);
            hsA += p0 + p1; hsB += p2 + p3;
            const int col = wn + nt * 8 + (lane & 3) * 2;
            const int ch = col >> 2;
            float* pA = Ps + rowA * 64 + ((ch ^ (rowA & 7)) << 2) + (col & 3);
            float* pB = Ps + rowB * 64 + ((ch ^ (rowB & 7)) << 2) + (col & 3);
            *(float2*)pA = make_float2(__uint_as_float(tf32r(p0)), __uint_as_float(tf32r(p1)));
            *(float2*)pB = make_float2(__uint_as_float(tf32r(p2)), __uint_as_float(tf32r(p3)));
        }
        hsA += __shfl_xor_sync(~0u, hsA, 1); hsA += __shfl_xor_sync(~0u, hsA, 2);
        hsB += __shfl_xor_sync(~0u, hsB, 1); hsB += __shfl_xor_sync(~0u, hsB, 2);
        if ((lane & 3) == 0) {
            sbuf[rowA * 2 + wg] = hsA;
            sbuf[rowB * 2 + wg] = hsB;
        }
        // rescale O accumulators while the publish lands
#pragma unroll
        for (int nt = 0; nt < 4; nt++) {
            acc_o[nt][0] *= alA; acc_o[nt][1] *= alA;
            acc_o[nt][2] *= alB; acc_o[nt][3] *= alB;
        }
        __syncthreads();
        lA = lA * alA + sbuf[rowA * 2] + sbuf[rowA * 2 + 1];
        lB = lB * alB + sbuf[rowB * 2] + sbuf[rowB * 2 + 1];

        // ---- O += P @ V (warp: rows wm..+15, dims wn..+31) ----
#pragma unroll
        for (int ks = 0; ks < 8; ks++) {
            unsigned pa[4];
            {
                const int sub = lane >> 3;
                const int row = wm + (sub & 1) * 8 + (lane & 7);
                const int kc = 2 * ks + (sub >> 1);
                ldsm4(pa, qsb + (uint32_t)(row * 64 + ((kc ^ (row & 7)) << 2)) * 4u);
            }
            unsigned vb[2][4];
#pragma unroll
            for (int bp = 0; bp < 2; bp++) {
                const int sub = lane >> 3;
                const int d = wn + bp * 16 + (sub >> 1) * 8 + (lane & 7);
                const int jc = 2 * ks + (sub & 1);
                const int ch = jc ^ (d & 7) ^ ((d >> 4) & 3);
                ldsm4(vb[bp], vtb + (uint32_t)(d * 64 + (ch << 2)) * 4u);
            }
#pragma unroll
            for (int nt = 0; nt < 4; nt++)
                mma8(acc_o[nt], pa, vb[nt >> 1][(nt & 1) * 2], vb[nt >> 1][(nt & 1) * 2 + 1]);
        }
    }

    // ---- epilogue ----
    const float liA = 1.0f / lA, liB = 1.0f / lB;
    float* opA = O + (size_t)(b * S_ + qt * 64 + rowA) * H_ + h * HD_ + wn + (lane & 3) * 2;
    float* opB = opA + 8 * (size_t)H_;
#pragma unroll
    for (int nt = 0; nt < 4; nt++) {
        *(float2*)(opA + nt * 8) = make_float2(acc_o[nt][0] * liA, acc_o[nt][1] * liA);
        *(float2*)(opB + nt * 8) = make_float2(acc_o[nt][2] * liB, acc_o[nt][3] * liB);
    }
}

// ---------------- launch ----------------
extern "C" void kernel_launch(void* const* d_in, const int* in_sizes, int n_in,
                              void* d_out, int out_size)
{
    const int*   pos  = (const int*)d_in[0];
    const float* hid  = (const float*)d_in[1];
    const float* wqkv = (const float*)d_in[2];
    const float* qw   = (const float*)d_in[3];
    const float* kw   = (const float*)d_in[4];
    const float* wo   = (const float*)d_in[5];
    float* out = (float*)d_out;

    float *qkv, *q, *k, *attnb;
    cudaGetSymbolAddress((void**)&qkv,   g_qkv);
    cudaGetSymbolAddress((void**)&q,     g_q);
    cudaGetSymbolAddress((void**)&k,     g_k);
    cudaGetSymbolAddress((void**)&attnb, g_attn);

    // 48 KB tiles + 1 KB for mbuf(512B) + sbuf(512B)  (R3 bug: only 512B extra)
    const int ATTN_SMEM = 49152 + 1024;
    cudaFuncSetAttribute(attn_mma,
                         cudaFuncAttributeMaxDynamicSharedMemorySize, ATTN_SMEM);

    // 1) qkv = hidden @ w_qkv^T
    dim3 g1(QKVN / 128, BS_ / 128);
    gemm_mma<<<g1, 256>>>(hid, wqkv, qkv, BS_, QKVN, H_);

    // 2) per-head LN + partial RoPE (+ fold score scale into Q, tf32 round)
    ln_rope<<<BS_ * 5, 256>>>(qkv, pos, qw, kw, q, k);

    // 3) causal GQA attention (tf32 mma flash)
    attn_mma<<<dim3(S_ / 64, B_ * NH_), 256, ATTN_SMEM>>>(q, k, qkv, attnb);

    // 4) out = attn @ w_o^T
    dim3 g2(H_ / 128, BS_ / 128);
    gemm_mma<<<g2, 256>>>(attnb, wo, out, BS_, H_, H_);
}

// round 6
// speedup vs baseline: 2.8881x; 1.0802x over previous
#include <cuda_runtime.h>
#include <cstdint>
#include <cstddef>

// Problem constants (fixed by setup_inputs)
#define B_   2
#define S_   2048
#define H_   2048
#define NH_  32
#define NKV_ 8
#define HD_  64
#define QKVN 3072
#define BS_  (B_ * S_)   // 4096

// ---------------- scratch (device globals: allocation-free) ----------------
__device__ __align__(16) float g_qkv[(size_t)BS_ * QKVN];
__device__ __align__(16) float g_q[(size_t)BS_ * NH_ * HD_];
__device__ __align__(16) float g_k[(size_t)BS_ * NKV_ * HD_];
__device__ __align__(16) float g_attn[(size_t)BS_ * NH_ * HD_];

// ---------------- helpers ----------------
__device__ __forceinline__ uint32_t smem_u32(const void* p) {
    uint32_t a;
    asm("{ .reg .u64 t; cvta.to.shared.u64 t, %1; cvt.u32.u64 %0, t; }" : "=r"(a) : "l"(p));
    return a;
}
__device__ __forceinline__ uint32_t tf32r(float f) {
    uint32_t r;
    asm("cvt.rna.tf32.f32 %0, %1;" : "=r"(r) : "f"(f));
    return r;
}
// m16n8k8 tf32 mma, fp32 accumulate (row.col)
__device__ __forceinline__ void mma8(float* d, const unsigned* a, unsigned b0, unsigned b1) {
    asm volatile(
        "mma.sync.aligned.m16n8k8.row.col.f32.tf32.tf32.f32 "
        "{%0,%1,%2,%3}, {%4,%5,%6,%7}, {%8,%9}, {%0,%1,%2,%3};"
        : "+f"(d[0]), "+f"(d[1]), "+f"(d[2]), "+f"(d[3])
        : "r"(a[0]), "r"(a[1]), "r"(a[2]), "r"(a[3]), "r"(b0), "r"(b1));
}
__device__ __forceinline__ void ldsm4(unsigned* r, uint32_t addr) {
    asm volatile("ldmatrix.sync.aligned.m8n8.x4.shared.b16 {%0,%1,%2,%3}, [%4];"
                 : "=r"(r[0]), "=r"(r[1]), "=r"(r[2]), "=r"(r[3]) : "r"(addr));
}

// ======================= tf32 mma GEMM: C = A[M,K] @ W[N,K]^T ===============
// (unchanged from R4 — 128x128 tile, BK=16, 8 warps, double-buffered)
__device__ __forceinline__ uint32_t gaddrA(uint32_t base, int m0, int ks, int lane) {
    int sub = lane >> 3;
    int row = m0 + (sub & 1) * 8 + (lane & 7);
    int kc  = 2 * ks + (sub >> 1);
    return base + (uint32_t)(row * 16 + ((kc ^ ((row >> 1) & 3)) << 2)) * 4u;
}
__device__ __forceinline__ uint32_t gaddrB(uint32_t base, int n0, int ks, int lane) {
    int sub = lane >> 3;
    int row = n0 + (sub >> 1) * 8 + (lane & 7);
    int kc  = 2 * ks + (sub & 1);
    return base + (uint32_t)(row * 16 + ((kc ^ ((row >> 1) & 3)) << 2)) * 4u;
}
__device__ __forceinline__ void stcvt(unsigned* buf, unsigned off, float4 v) {
    uint4 u = make_uint4(tf32r(v.x), tf32r(v.y), tf32r(v.z), tf32r(v.w));
    *(uint4*)(buf + off) = u;
}

__global__ __launch_bounds__(256) void gemm_mma(
    const float* __restrict__ A, const float* __restrict__ W,
    float* __restrict__ C, int M, int N, int K)
{
    __shared__ __align__(16) unsigned As[2][2048];
    __shared__ __align__(16) unsigned Bs[2][2048];
    const int tid = threadIdx.x, lane = tid & 31, wid = tid >> 5;
    const int bm = blockIdx.y * 128, bn = blockIdx.x * 128;
    const int wm = (wid & 1) * 64, wn = (wid >> 1) * 32;

    const int tr = tid >> 1;
    const int tc = (tid & 1) * 2;
    const float* Ap = A + (size_t)(bm + tr) * K + tc * 4;
    const float* Wp = W + (size_t)(bn + tr) * K + tc * 4;
    const unsigned so0 = tr * 16 + (((tc    ) ^ ((tr >> 1) & 3)) << 2);
    const unsigned so1 = tr * 16 + (((tc + 1) ^ ((tr >> 1) & 3)) << 2);

    const uint32_t asb[2] = { smem_u32(As[0]), smem_u32(As[1]) };
    const uint32_t bsb[2] = { smem_u32(Bs[0]), smem_u32(Bs[1]) };

    float acc[16][4];
#pragma unroll
    for (int i = 0; i < 16; i++)
#pragma unroll
        for (int j = 0; j < 4; j++) acc[i][j] = 0.0f;

    float4 a0 = *(const float4*)Ap,       a1 = *(const float4*)(Ap + 4);
    float4 w0 = *(const float4*)Wp,       w1 = *(const float4*)(Wp + 4);
    stcvt(As[0], so0, a0); stcvt(As[0], so1, a1);
    stcvt(Bs[0], so0, w0); stcvt(Bs[0], so1, w1);

    const int T = K >> 4;
    for (int t = 0; t < T; t++) {
        __syncthreads();
        if (t + 1 < T) {
            const float* ap = Ap + (t + 1) * 16;
            const float* wp = Wp + (t + 1) * 16;
            a0 = *(const float4*)ap; a1 = *(const float4*)(ap + 4);
            w0 = *(const float4*)wp; w1 = *(const float4*)(wp + 4);
        }
        const int buf = t & 1;
#pragma unroll
        for (int ks = 0; ks < 2; ks++) {
            unsigned af[4][4], bf[2][4];
#pragma unroll
            for (int mt = 0; mt < 4; mt++)
                ldsm4(af[mt], gaddrA(asb[buf], wm + mt * 16, ks, lane));
#pragma unroll
            for (int bp = 0; bp < 2; bp++)
                ldsm4(bf[bp], gaddrB(bsb[buf], wn + bp * 16, ks, lane));
#pragma unroll
            for (int mt = 0; mt < 4; mt++)
#pragma unroll
                for (int nt = 0; nt < 4; nt++)
                    mma8(acc[mt * 4 + nt], af[mt],
                         bf[nt >> 1][(nt & 1) * 2], bf[nt >> 1][(nt & 1) * 2 + 1]);
        }
        __syncthreads();
        if (t + 1 < T) {
            const int nb = (t + 1) & 1;
            stcvt(As[nb], so0, a0); stcvt(As[nb], so1, a1);
            stcvt(Bs[nb], so0, w0); stcvt(Bs[nb], so1, w1);
        }
    }

#pragma unroll
    for (int mt = 0; mt < 4; mt++) {
        const int rA = bm + wm + mt * 16 + (lane >> 2);
        float* cA = C + (size_t)rA * N + bn + wn + (lane & 3) * 2;
        float* cB = cA + 8 * (size_t)N;
#pragma unroll
        for (int nt = 0; nt < 4; nt++) {
            *(float2*)(cA + nt * 8) = make_float2(acc[mt * 4 + nt][0], acc[mt * 4 + nt][1]);
            *(float2*)(cB + nt * 8) = make_float2(acc[mt * 4 + nt][2], acc[mt * 4 + nt][3]);
        }
    }
}

// ---------------- fused per-head LayerNorm + partial NeoX RoPE ----------------
__global__ __launch_bounds__(256) void ln_rope(
    const float* __restrict__ qkv, const int* __restrict__ pos_ids,
    const float* __restrict__ qw, const float* __restrict__ kw,
    float* __restrict__ qo, float* __restrict__ ko)
{
    const int wid = threadIdx.x >> 5;
    const int lane = threadIdx.x & 31;
    const int bs = blockIdx.x / 5;
    const int head = (blockIdx.x % 5) * 8 + wid;   // 0..39 (32 Q + 8 K)

    const float* src = qkv + (size_t)bs * QKVN + head * HD_;
    float v0 = src[lane], v1 = src[lane + 32];

    float s = v0 + v1;
#pragma unroll
    for (int m = 16; m; m >>= 1) s += __shfl_xor_sync(~0u, s, m);
    const float mu = s * (1.0f / 64.0f);
    const float d0 = v0 - mu, d1 = v1 - mu;
    float vs = d0 * d0 + d1 * d1;
#pragma unroll
    for (int m = 16; m; m >>= 1) vs += __shfl_xor_sync(~0u, vs, m);
    const float inv = rsqrtf(vs * (1.0f / 64.0f) + 1e-5f);

    const float* w = (head < NH_) ? (qw + head * HD_) : (kw + (head - NH_) * HD_);
    float n0 = d0 * inv * w[lane];
    float n1 = d1 * inv * w[lane + 32];

    const float p = (float)pos_ids[bs];
    const float partner = __shfl_xor_sync(~0u, n0, 8);
    if (lane < 16) {
        const int i = lane & 7;
        const float invf = powf(10000.0f, -(float)i * 0.125f);
        const float ang = p * invf;
        const float c = cosf(ang), sn = sinf(ang);
        n0 = (lane < 8) ? (n0 * c - partner * sn) : (n0 * c + partner * sn);
    }
    const float sc = (head < NH_) ? 0.125f : 1.0f;   // HEAD_DIM^-0.5 folded into Q
    n0 = __uint_as_float(tf32r(n0 * sc));
    n1 = __uint_as_float(tf32r(n1 * sc));

    if (head < NH_) {
        float* dst = qo + ((size_t)bs * NH_ + head) * HD_;
        dst[lane] = n0; dst[lane + 32] = n1;
    } else {
        float* dst = ko + ((size_t)bs * NKV_ + (head - NH_)) * HD_;
        dst[lane] = n0; dst[lane + 32] = n1;
    }
}

// ======================= flash attention v2 (tf32 mma) =======================
// CTA: 128 q-rows x (b,h); KV tiles of 64. 8 warps: wq=(wid&3)*32 rows,
// wg=(wid>>2) key half. K stored with per-8-group permuted key rows
// (phys 2j<->logical j, 2j+1<->j+4) so the S accumulator IS the P A-fragment
// after the {c0,c2,c1,c3} register reorder (c-layout cols 2t/2t+1 = logical
// keys t/t+4; A-frag a0..a3 = (g,t),(g+8,t),(g,t+4),(g+8,t+4)).
__global__ __launch_bounds__(256) void attn_mma2(
    const float* __restrict__ Q, const float* __restrict__ Kg,
    const float* __restrict__ qkv, float* __restrict__ O)
{
    extern __shared__ __align__(16) char smraw[];
    float* Qs = (float*)smraw;                  // [128][64] 32KB
    float* Ks = (float*)(smraw + 32768);        // [64][64] 16KB (key rows permuted)
    float* Vt = (float*)(smraw + 49152);        // [64][64] 16KB (canonical, transposed)
    float* mbuf = (float*)(smraw + 65536);      // [128][2]
    float* sbuf = mbuf + 256;                   // [128][2]
    float* Ps   = (float*)smraw;                // epilogue staging, stride 68 (reuses Qs+Ks)

    const uint32_t qsb = smem_u32(Qs);
    const uint32_t ksb = smem_u32(Ks);
    const uint32_t vtb = smem_u32(Vt);

    const int qt = (int)gridDim.x - 1 - (int)blockIdx.x;   // heavy tiles first
    const int bh = blockIdx.y;
    const int b = bh >> 5, h = bh & 31, kh = h >> 2;
    const int tid = threadIdx.x, lane = tid & 31, wid = tid >> 5;
    const int wm = (wid & 3) * 32;
    const int wg = wid >> 2;
    const int wn = wg * 32;

    // ---- load Q tile 128x64 (already tf32-rounded by ln_rope) ----
    {
        const int r = tid >> 1;
        const int hb = (tid & 1) * 8;   // chunk base (8 chunks of 4 floats)
        const float* qp = Q + ((size_t)(b * S_ + qt * 128 + r) * NH_ + h) * HD_ + hb * 4;
#pragma unroll
        for (int l = 0; l < 8; l++) {
            float4 v = *(const float4*)(qp + l * 4);
            *(float4*)(Qs + r * 64 + (((hb + l) ^ (r & 7)) << 2)) = v;
        }
    }
    __syncthreads();

    // ---- hoist Q A-fragments (rows wm..wm+31, invariant across kt) ----
    unsigned qa[8][2][4];
#pragma unroll
    for (int ks = 0; ks < 8; ks++)
#pragma unroll
        for (int mt = 0; mt < 2; mt++) {
            const int sub = lane >> 3;
            const int row = wm + mt * 16 + (sub & 1) * 8 + (lane & 7);
            const int kc = 2 * ks + (sub >> 1);
            ldsm4(qa[ks][mt], qsb + (uint32_t)(row * 64 + ((kc ^ (row & 7)) << 2)) * 4u);
        }

    float acc_o[2][8][4];
#pragma unroll
    for (int mt = 0; mt < 2; mt++)
#pragma unroll
        for (int n8 = 0; n8 < 8; n8++)
#pragma unroll
            for (int e = 0; e < 4; e++) acc_o[mt][n8][e] = 0.0f;
    float m_[2][2] = { { -1e30f, -1e30f }, { -1e30f, -1e30f } };
    float l_[2][2] = { { 0.0f, 0.0f }, { 0.0f, 0.0f } };

    const int ktmax = 2 * qt + 1;
    for (int kt = 0; kt <= ktmax; kt++) {
        // ---- global loads (K tile + V tile, 64x64 each) ----
        const int r = tid >> 2;
        const int cb = (tid & 3) * 4;    // chunk base
        const float* kp = Kg + ((size_t)(b * S_ + kt * 64 + r) * NKV_ + kh) * HD_ + cb * 4;
        const float* vp = qkv + (size_t)(b * S_ + kt * 64 + r) * QKVN + 2560 + kh * HD_ + cb * 4;
        float4 kv[4], vv[4];
#pragma unroll
        for (int l = 0; l < 4; l++) { kv[l] = *(const float4*)(kp + l * 4);
                                      vv[l] = *(const float4*)(vp + l * 4); }
        __syncthreads();   // prior iteration done with Ks/Vt

        // K store: permuted rows within each 8-key group: phys = 2*(l&3) + (l>>2)
        {
            const int l3 = r & 7;
            const int rp = (r & 56) | ((l3 & 3) * 2 + (l3 >> 2));
#pragma unroll
            for (int l = 0; l < 4; l++)
                *(float4*)(Ks + rp * 64 + (((cb + l) ^ (rp & 7)) << 2)) = kv[l];
        }
        // V store: transposed [d][key], canonical key order, tf32-rounded
#pragma unroll
        for (int l = 0; l < 4; l++) {
            const float vals[4] = { vv[l].x, vv[l].y, vv[l].z, vv[l].w };
#pragma unroll
            for (int jj = 0; jj < 4; jj++) {
                const int d = cb * 4 + l * 4 + jj;
                const int ch = (r >> 2) ^ (d & 7) ^ ((d >> 4) & 3);
                Vt[d * 64 + (ch << 2) + (r & 3)] = __uint_as_float(tf32r(vals[jj]));
            }
        }
        __syncthreads();

        // ---- S = Q @ K^T (warp: 32 rows x 32 keys) ----
        float sacc[2][4][4];
#pragma unroll
        for (int mt = 0; mt < 2; mt++)
#pragma unroll
            for (int nt = 0; nt < 4; nt++)
#pragma unroll
                for (int e = 0; e < 4; e++) sacc[mt][nt][e] = 0.0f;
#pragma unroll
        for (int ks = 0; ks < 8; ks++) {
#pragma unroll
            for (int bp = 0; bp < 2; bp++) {
                unsigned kbf[4];
                const int sub = lane >> 3;
                const int row = wn + bp * 16 + (sub >> 1) * 8 + (lane & 7);
                const int kc = 2 * ks + (sub & 1);
                ldsm4(kbf, ksb + (uint32_t)(row * 64 + ((kc ^ (row & 7)) << 2)) * 4u);
#pragma unroll
                for (int mt = 0; mt < 2; mt++) {
                    mma8(sacc[mt][bp * 2],     qa[ks][mt], kbf[0], kbf[1]);
                    mma8(sacc[mt][bp * 2 + 1], qa[ks][mt], kbf[2], kbf[3]);
                }
            }
        }

        // ---- causal mask (permuted cols: c0/c2 -> key t, c1/c3 -> key t+4) ----
        const int koff = kt * 64 - qt * 128;
        if (koff >= 0) {
#pragma unroll
            for (int mt = 0; mt < 2; mt++) {
                const int rA = wm + mt * 16 + (lane >> 2);
                const int rB = rA + 8;
#pragma unroll
                for (int nt = 0; nt < 4; nt++) {
                    const int k0 = koff + wn + nt * 8 + (lane & 3);
                    const int k1 = k0 + 4;
                    if (k0 > rA) sacc[mt][nt][0] = -1e30f;
                    if (k1 > rA) sacc[mt][nt][1] = -1e30f;
                    if (k0 > rB) sacc[mt][nt][2] = -1e30f;
                    if (k1 > rB) sacc[mt][nt][3] = -1e30f;
                }
            }
        }

        // ---- half-row max, publish ----
#pragma unroll
        for (int mt = 0; mt < 2; mt++) {
            float hmA = -1e30f, hmB = -1e30f;
#pragma unroll
            for (int nt = 0; nt < 4; nt++) {
                hmA = fmaxf(hmA, fmaxf(sacc[mt][nt][0], sacc[mt][nt][1]));
                hmB = fmaxf(hmB, fmaxf(sacc[mt][nt][2], sacc[mt][nt][3]));
            }
            hmA = fmaxf(hmA, __shfl_xor_sync(~0u, hmA, 1));
            hmA = fmaxf(hmA, __shfl_xor_sync(~0u, hmA, 2));
            hmB = fmaxf(hmB, __shfl_xor_sync(~0u, hmB, 1));
            hmB = fmaxf(hmB, __shfl_xor_sync(~0u, hmB, 2));
            if ((lane & 3) == 0) {
                mbuf[(wm + mt * 16 + (lane >> 2)) * 2 + wg] = hmA;
                mbuf[(wm + mt * 16 + 8 + (lane >> 2)) * 2 + wg] = hmB;
            }
        }
        __syncthreads();

        // ---- combine maxes, exp (in place -> tf32), half sums ----
        float alA[2], alB[2];
#pragma unroll
        for (int mt = 0; mt < 2; mt++) {
            const int rA = wm + mt * 16 + (lane >> 2);
            const int rB = rA + 8;
            const float mnA = fmaxf(m_[mt][0], fmaxf(mbuf[rA * 2], mbuf[rA * 2 + 1]));
            const float mnB = fmaxf(m_[mt][1], fmaxf(mbuf[rB * 2], mbuf[rB * 2 + 1]));
            alA[mt] = __expf(m_[mt][0] - mnA);
            alB[mt] = __expf(m_[mt][1] - mnB);
            m_[mt][0] = mnA; m_[mt][1] = mnB;
            float hsA = 0.0f, hsB = 0.0f;
#pragma unroll
            for (int nt = 0; nt < 4; nt++) {
                const float p0 = __expf(sacc[mt][nt][0] - mnA);
                const float p1 = __expf(sacc[mt][nt][1] - mnA);
                const float p2 = __expf(sacc[mt][nt][2] - mnB);
                const float p3 = __expf(sacc[mt][nt][3] - mnB);
                hsA += p0 + p1; hsB += p2 + p3;
                sacc[mt][nt][0] = __uint_as_float(tf32r(p0));
                sacc[mt][nt][1] = __uint_as_float(tf32r(p1));
                sacc[mt][nt][2] = __uint_as_float(tf32r(p2));
                sacc[mt][nt][3] = __uint_as_float(tf32r(p3));
            }
            hsA += __shfl_xor_sync(~0u, hsA, 1); hsA += __shfl_xor_sync(~0u, hsA, 2);
            hsB += __shfl_xor_sync(~0u, hsB, 1); hsB += __shfl_xor_sync(~0u, hsB, 2);
            if ((lane & 3) == 0) {
                sbuf[rA * 2 + wg] = hsA;
                sbuf[rB * 2 + wg] = hsB;
            }
        }
        // rescale O partials while sums publish
#pragma unroll
        for (int mt = 0; mt < 2; mt++)
#pragma unroll
            for (int n8 = 0; n8 < 8; n8++) {
                acc_o[mt][n8][0] *= alA[mt]; acc_o[mt][n8][1] *= alA[mt];
                acc_o[mt][n8][2] *= alB[mt]; acc_o[mt][n8][3] *= alB[mt];
            }
        __syncthreads();
#pragma unroll
        for (int mt = 0; mt < 2; mt++) {
            const int rA = wm + mt * 16 + (lane >> 2);
            const int rB = rA + 8;
            l_[mt][0] = l_[mt][0] * alA[mt] + sbuf[rA * 2] + sbuf[rA * 2 + 1];
            l_[mt][1] = l_[mt][1] * alB[mt] + sbuf[rB * 2] + sbuf[rB * 2 + 1];
        }

        // ---- O += P @ V (P = sacc regs, reordered {c0,c2,c1,c3} -> A-frag) ----
#pragma unroll
        for (int ntb = 0; ntb < 4; ntb++) {
            const int kb8 = wg * 4 + ntb;
#pragma unroll
            for (int bp = 0; bp < 4; bp++) {
                unsigned vb[4];
                const int sub = lane >> 3;
                const int d = bp * 16 + (sub >> 1) * 8 + (lane & 7);
                const int jc = 2 * kb8 + (sub & 1);
                const int ch = jc ^ (d & 7) ^ ((d >> 4) & 3);
                ldsm4(vb, vtb + (uint32_t)(d * 64 + (ch << 2)) * 4u);
#pragma unroll
                for (int mt = 0; mt < 2; mt++) {
                    const unsigned* u = (const unsigned*)sacc[mt][ntb];
                    const unsigned pa[4] = { u[0], u[2], u[1], u[3] };   // c->A reorder
                    mma8(acc_o[mt][bp * 2],     pa, vb[0], vb[1]);
                    mma8(acc_o[mt][bp * 2 + 1], pa, vb[2], vb[3]);
                }
            }
        }
    }

    // ---- epilogue: combine the two key-half partials, scale by 1/l ----
    if (wg == 1) {
#pragma unroll
        for (int mt = 0; mt < 2; mt++) {
            const int rA = wm + mt * 16 + (lane >> 2);
            const int rB = rA + 8;
#pragma unroll
            for (int n8 = 0; n8 < 8; n8++) {
                const int d0 = n8 * 8 + (lane & 3) * 2;
                *(float2*)(Ps + rA * 68 + d0) = make_float2(acc_o[mt][n8][0], acc_o[mt][n8][1]);
                *(float2*)(Ps + rB * 68 + d0) = make_float2(acc_o[mt][n8][2], acc_o[mt][n8][3]);
            }
        }
    }
    __syncthreads();
    if (wg == 0) {
#pragma unroll
        for (int mt = 0; mt < 2; mt++) {
            const int rA = wm + mt * 16 + (lane >> 2);
            const int rB = rA + 8;
            const float liA = 1.0f / l_[mt][0];
            const float liB = 1.0f / l_[mt][1];
            float* oA = O + (size_t)(b * S_ + qt * 128 + rA) * H_ + h * HD_;
            float* oB = O + (size_t)(b * S_ + qt * 128 + rB) * H_ + h * HD_;
#pragma unroll
            for (int n8 = 0; n8 < 8; n8++) {
                const int d0 = n8 * 8 + (lane & 3) * 2;
                const float2 pA = *(const float2*)(Ps + rA * 68 + d0);
                const float2 pB = *(const float2*)(Ps + rB * 68 + d0);
                *(float2*)(oA + d0) = make_float2((acc_o[mt][n8][0] + pA.x) * liA,
                                                  (acc_o[mt][n8][1] + pA.y) * liA);
                *(float2*)(oB + d0) = make_float2((acc_o[mt][n8][2] + pB.x) * liB,
                                                  (acc_o[mt][n8][3] + pB.y) * liB);
            }
        }
    }
}

// ---------------- launch ----------------
extern "C" void kernel_launch(void* const* d_in, const int* in_sizes, int n_in,
                              void* d_out, int out_size)
{
    const int*   pos  = (const int*)d_in[0];
    const float* hid  = (const float*)d_in[1];
    const float* wqkv = (const float*)d_in[2];
    const float* qw   = (const float*)d_in[3];
    const float* kw   = (const float*)d_in[4];
    const float* wo   = (const float*)d_in[5];
    float* out = (float*)d_out;

    float *qkv, *q, *k, *attnb;
    cudaGetSymbolAddress((void**)&qkv,   g_qkv);
    cudaGetSymbolAddress((void**)&q,     g_q);
    cudaGetSymbolAddress((void**)&k,     g_k);
    cudaGetSymbolAddress((void**)&attnb, g_attn);

    const int ATTN_SMEM = 65536 + 2048;   // Qs+Ks+Vt + mbuf+sbuf
    cudaFuncSetAttribute(attn_mma2,
                         cudaFuncAttributeMaxDynamicSharedMemorySize, ATTN_SMEM);

    // 1) qkv = hidden @ w_qkv^T
    dim3 g1(QKVN / 128, BS_ / 128);
    gemm_mma<<<g1, 256>>>(hid, wqkv, qkv, BS_, QKVN, H_);

    // 2) per-head LN + partial RoPE (+ fold score scale into Q, tf32 round)
    ln_rope<<<BS_ * 5, 256>>>(qkv, pos, qw, kw, q, k);

    // 3) causal GQA attention (tf32 mma flash v2, 128-row CTAs)
    attn_mma2<<<dim3(S_ / 128, B_ * NH_), 256, ATTN_SMEM>>>(q, k, qkv, attnb);

    // 4) out = attn @ w_o^T
    dim3 g2(H_ / 128, BS_ / 128);
    gemm_mma<<<g2, 256>>>(attnb, wo, out, BS_, H_, H_);
}

// round 8
// speedup vs baseline: 2.9542x; 1.0229x over previous
#include <cuda_runtime.h>
#include <cstdint>
#include <cstddef>

// Problem constants (fixed by setup_inputs)
#define B_   2
#define S_   2048
#define H_   2048
#define NH_  32
#define NKV_ 8
#define HD_  64
#define QKVN 3072
#define BS_  (B_ * S_)   // 4096

// ---------------- scratch (device globals: allocation-free) ----------------
__device__ __align__(16) float g_qkv[(size_t)BS_ * QKVN];
__device__ __align__(16) float g_q[(size_t)BS_ * NH_ * HD_];
__device__ __align__(16) float g_k[(size_t)BS_ * NKV_ * HD_];
__device__ __align__(16) float g_v[(size_t)BS_ * NKV_ * HD_];   // [b][kh][d][s], tf32
__device__ __align__(16) float g_attn[(size_t)BS_ * NH_ * HD_];

// ---------------- helpers ----------------
__device__ __forceinline__ uint32_t smem_u32(const void* p) {
    uint32_t a;
    asm("{ .reg .u64 t; cvta.to.shared.u64 t, %1; cvt.u32.u64 %0, t; }" : "=r"(a) : "l"(p));
    return a;
}
__device__ __forceinline__ uint32_t tf32r(float f) {
    uint32_t r;
    asm("cvt.rna.tf32.f32 %0, %1;" : "=r"(r) : "f"(f));
    return r;
}
// m16n8k8 tf32 mma, fp32 accumulate (row.col)
__device__ __forceinline__ void mma8(float* d, const unsigned* a, unsigned b0, unsigned b1) {
    asm volatile(
        "mma.sync.aligned.m16n8k8.row.col.f32.tf32.tf32.f32 "
        "{%0,%1,%2,%3}, {%4,%5,%6,%7}, {%8,%9}, {%0,%1,%2,%3};"
        : "+f"(d[0]), "+f"(d[1]), "+f"(d[2]), "+f"(d[3])
        : "r"(a[0]), "r"(a[1]), "r"(a[2]), "r"(a[3]), "r"(b0), "r"(b1));
}
__device__ __forceinline__ void ldsm4(unsigned* r, uint32_t addr) {
    asm volatile("ldmatrix.sync.aligned.m8n8.x4.shared.b16 {%0,%1,%2,%3}, [%4];"
                 : "=r"(r[0]), "=r"(r[1]), "=r"(r[2]), "=r"(r[3]) : "r"(addr));
}
__device__ __forceinline__ void cpa16(uint32_t dst, const void* src) {
    asm volatile("cp.async.cg.shared.global [%0], [%1], 16;" :: "r"(dst), "l"(src) : "memory");
}
__device__ __forceinline__ void cpa_commit() {
    asm volatile("cp.async.commit_group;" ::: "memory");
}
__device__ __forceinline__ void cpa_wait0() {
    asm volatile("cp.async.wait_group 0;" ::: "memory");
}

// ======================= tf32 mma GEMM: C = A[M,K] @ W[N,K]^T ===============
// (unchanged — 128x128 tile, BK=16, 8 warps, double-buffered)
__device__ __forceinline__ uint32_t gaddrA(uint32_t base, int m0, int ks, int lane) {
    int sub = lane >> 3;
    int row = m0 + (sub & 1) * 8 + (lane & 7);
    int kc  = 2 * ks + (sub >> 1);
    return base + (uint32_t)(row * 16 + ((kc ^ ((row >> 1) & 3)) << 2)) * 4u;
}
__device__ __forceinline__ uint32_t gaddrB(uint32_t base, int n0, int ks, int lane) {
    int sub = lane >> 3;
    int row = n0 + (sub >> 1) * 8 + (lane & 7);
    int kc  = 2 * ks + (sub & 1);
    return base + (uint32_t)(row * 16 + ((kc ^ ((row >> 1) & 3)) << 2)) * 4u;
}
__device__ __forceinline__ void stcvt(unsigned* buf, unsigned off, float4 v) {
    uint4 u = make_uint4(tf32r(v.x), tf32r(v.y), tf32r(v.z), tf32r(v.w));
    *(uint4*)(buf + off) = u;
}

__global__ __launch_bounds__(256) void gemm_mma(
    const float* __restrict__ A, const float* __restrict__ W,
    float* __restrict__ C, int M, int N, int K)
{
    __shared__ __align__(16) unsigned As[2][2048];
    __shared__ __align__(16) unsigned Bs[2][2048];
    const int tid = threadIdx.x, lane = tid & 31, wid = tid >> 5;
    const int bm = blockIdx.y * 128, bn = blockIdx.x * 128;
    const int wm = (wid & 1) * 64, wn = (wid >> 1) * 32;

    const int tr = tid >> 1;
    const int tc = (tid & 1) * 2;
    const float* Ap = A + (size_t)(bm + tr) * K + tc * 4;
    const float* Wp = W + (size_t)(bn + tr) * K + tc * 4;
    const unsigned so0 = tr * 16 + (((tc    ) ^ ((tr >> 1) & 3)) << 2);
    const unsigned so1 = tr * 16 + (((tc + 1) ^ ((tr >> 1) & 3)) << 2);

    const uint32_t asb[2] = { smem_u32(As[0]), smem_u32(As[1]) };
    const uint32_t bsb[2] = { smem_u32(Bs[0]), smem_u32(Bs[1]) };

    float acc[16][4];
#pragma unroll
    for (int i = 0; i < 16; i++)
#pragma unroll
        for (int j = 0; j < 4; j++) acc[i][j] = 0.0f;

    float4 a0 = *(const float4*)Ap,       a1 = *(const float4*)(Ap + 4);
    float4 w0 = *(const float4*)Wp,       w1 = *(const float4*)(Wp + 4);
    stcvt(As[0], so0, a0); stcvt(As[0], so1, a1);
    stcvt(Bs[0], so0, w0); stcvt(Bs[0], so1, w1);

    const int T = K >> 4;
    for (int t = 0; t < T; t++) {
        __syncthreads();
        if (t + 1 < T) {
            const float* ap = Ap + (t + 1) * 16;
            const float* wp = Wp + (t + 1) * 16;
            a0 = *(const float4*)ap; a1 = *(const float4*)(ap + 4);
            w0 = *(const float4*)wp; w1 = *(const float4*)(wp + 4);
        }
        const int buf = t & 1;
#pragma unroll
        for (int ks = 0; ks < 2; ks++) {
            unsigned af[4][4], bf[2][4];
#pragma unroll
            for (int mt = 0; mt < 4; mt++)
                ldsm4(af[mt], gaddrA(asb[buf], wm + mt * 16, ks, lane));
#pragma unroll
            for (int bp = 0; bp < 2; bp++)
                ldsm4(bf[bp], gaddrB(bsb[buf], wn + bp * 16, ks, lane));
#pragma unroll
            for (int mt = 0; mt < 4; mt++)
#pragma unroll
                for (int nt = 0; nt < 4; nt++)
                    mma8(acc[mt * 4 + nt], af[mt],
                         bf[nt >> 1][(nt & 1) * 2], bf[nt >> 1][(nt & 1) * 2 + 1]);
        }
        __syncthreads();
        if (t + 1 < T) {
            const int nb = (t + 1) & 1;
            stcvt(As[nb], so0, a0); stcvt(As[nb], so1, a1);
            stcvt(Bs[nb], so0, w0); stcvt(Bs[nb], so1, w1);
        }
    }

#pragma unroll
    for (int mt = 0; mt < 4; mt++) {
        const int rA = bm + wm + mt * 16 + (lane >> 2);
        float* cA = C + (size_t)rA * N + bn + wn + (lane & 3) * 2;
        float* cB = cA + 8 * (size_t)N;
#pragma unroll
        for (int nt = 0; nt < 4; nt++) {
            *(float2*)(cA + nt * 8) = make_float2(acc[mt * 4 + nt][0], acc[mt * 4 + nt][1]);
            *(float2*)(cB + nt * 8) = make_float2(acc[mt * 4 + nt][2], acc[mt * 4 + nt][3]);
        }
    }
}

// ---------------- fused per-head LayerNorm + partial NeoX RoPE ----------------
__global__ __launch_bounds__(256) void ln_rope(
    const float* __restrict__ qkv, const int* __restrict__ pos_ids,
    const float* __restrict__ qw, const float* __restrict__ kw,
    float* __restrict__ qo, float* __restrict__ ko)
{
    const int wid = threadIdx.x >> 5;
    const int lane = threadIdx.x & 31;
    const int bs = blockIdx.x / 5;
    const int head = (blockIdx.x % 5) * 8 + wid;   // 0..39 (32 Q + 8 K)

    const float* src = qkv + (size_t)bs * QKVN + head * HD_;
    float v0 = src[lane], v1 = src[lane + 32];

    float s = v0 + v1;
#pragma unroll
    for (int m = 16; m; m >>= 1) s += __shfl_xor_sync(~0u, s, m);
    const float mu = s * (1.0f / 64.0f);
    const float d0 = v0 - mu, d1 = v1 - mu;
    float vs = d0 * d0 + d1 * d1;
#pragma unroll
    for (int m = 16; m; m >>= 1) vs += __shfl_xor_sync(~0u, vs, m);
    const float inv = rsqrtf(vs * (1.0f / 64.0f) + 1e-5f);

    const float* w = (head < NH_) ? (qw + head * HD_) : (kw + (head - NH_) * HD_);
    float n0 = d0 * inv * w[lane];
    float n1 = d1 * inv * w[lane + 32];

    const float p = (float)pos_ids[bs];
    const float partner = __shfl_xor_sync(~0u, n0, 8);
    if (lane < 16) {
        const int i = lane & 7;
        const float invf = powf(10000.0f, -(float)i * 0.125f);
        const float ang = p * invf;
        const float c = cosf(ang), sn = sinf(ang);
        n0 = (lane < 8) ? (n0 * c - partner * sn) : (n0 * c + partner * sn);
    }
    const float sc = (head < NH_) ? 0.125f : 1.0f;   // HEAD_DIM^-0.5 folded into Q
    n0 = __uint_as_float(tf32r(n0 * sc));
    n1 = __uint_as_float(tf32r(n1 * sc));

    if (head < NH_) {
        float* dst = qo + ((size_t)bs * NH_ + head) * HD_;
        dst[lane] = n0; dst[lane + 32] = n1;
    } else {
        float* dst = ko + ((size_t)bs * NKV_ + (head - NH_)) * HD_;
        dst[lane] = n0; dst[lane + 32] = n1;
    }
}

// ---------------- prep_v: transpose V to [b][kh][d][s] with tf32 round -------
__global__ __launch_bounds__(256) void prep_v(
    const float* __restrict__ qkv, float* __restrict__ V)
{
    __shared__ float ts[64][65];
    const int bkh = blockIdx.y;             // 0..15
    const int b = bkh >> 3, kh = bkh & 7;
    const int s0 = blockIdx.x * 64;
    const int r  = threadIdx.x >> 2;        // 0..63
    const int c0 = (threadIdx.x & 3) * 16;

    const float* src = qkv + (size_t)(b * S_ + s0 + r) * QKVN + 2560 + kh * 64 + c0;
#pragma unroll
    for (int l = 0; l < 4; l++) {
        float4 v = *(const float4*)(src + l * 4);
        ts[r][c0 + l * 4 + 0] = __uint_as_float(tf32r(v.x));
        ts[r][c0 + l * 4 + 1] = __uint_as_float(tf32r(v.y));
        ts[r][c0 + l * 4 + 2] = __uint_as_float(tf32r(v.z));
        ts[r][c0 + l * 4 + 3] = __uint_as_float(tf32r(v.w));
    }
    __syncthreads();

    const int d  = threadIdx.x >> 2;
    const int sc = (threadIdx.x & 3) * 16;
    float* dst = V + ((size_t)(b * NKV_ + kh) * HD_ + d) * S_ + s0 + sc;
#pragma unroll
    for (int l = 0; l < 4; l++) {
        float4 w = make_float4(ts[sc + l * 4 + 0][d], ts[sc + l * 4 + 1][d],
                               ts[sc + l * 4 + 2][d], ts[sc + l * 4 + 3][d]);
        *(float4*)(dst + l * 4) = w;
    }
}

// ======================= flash attention v3 (tf32 mma + cp.async) ============
// CTA: 128 q-rows x (b,h); KV tiles of 64, double-buffered via cp.async.
// 8 warps: rows (wid&3)*32, key half wg=(wid>>2). K rows stored permuted
// (phys 2j<->j, 2j+1<->j+4) so S accumulators are PV A-frags after the
// {c0,c2,c1,c3} reorder. V pre-transposed in gmem ([d][s]) -> direct cp.async.
//
// smem layout (bytes):
//   [0, 32768)          Qs [128][64]   (aliased as epilogue Ps, stride 68)
//   [32768, 49152)      Ks buf0        [49152, 65536)  Ks buf1
//   [65536, 81920)      Vt buf0        [81920, 98304)  Vt buf1
//   [98304, 99328)      mbuf [128][2]
//   [99328, 100352)     sbuf [128][2]
#define ATTN_SMEM_BYTES (98304 + 2048)

__global__ __launch_bounds__(256) void attn_mma3(
    const float* __restrict__ Q, const float* __restrict__ Kg,
    const float* __restrict__ Vg, float* __restrict__ O)
{
    extern __shared__ __align__(16) char smraw[];
    float* Qs = (float*)smraw;                              // [128][64] 32KB
    const uint32_t qsb = smem_u32(smraw);
    const uint32_t ksb[2] = { qsb + 32768u, qsb + 49152u }; // [64][64] x2
    const uint32_t vtb[2] = { qsb + 65536u, qsb + 81920u }; // [64][64] x2
    float* mbuf = (float*)(smraw + 98304);                  // [128][2] = 1KB
    float* sbuf = (float*)(smraw + 99328);                  // [128][2] = 1KB
    float* Ps   = (float*)smraw;                            // epilogue staging (stride 68)

    const int qt = (int)gridDim.x - 1 - (int)blockIdx.x;    // heavy tiles first
    const int bh = blockIdx.y;
    const int b = bh >> 5, h = bh & 31, kh = h >> 2;
    const int tid = threadIdx.x, lane = tid & 31, wid = tid >> 5;
    const int wm = (wid & 3) * 32;
    const int wg = wid >> 2;
    const int wn = wg * 32;

    // per-thread cp.async assignment: row cr (0..63), 16B chunks cb..cb+3 (0..15)
    const int cr = tid >> 2;
    const int cb = (tid & 3) * 4;
    const int crl = cr & 7;
    const int crp = (cr & 56) | ((crl & 3) * 2 + (crl >> 2));   // permuted K row
    const uint32_t kswz = (uint32_t)(crp & 7);
    const uint32_t vswz = (uint32_t)((cr & 7) ^ ((cr >> 4) & 3));
    const float* vrow = Vg + ((size_t)(b * NKV_ + kh) * HD_ + cr) * S_;

    // ---- issue KV tile 0 (overlaps the Q load) ----
    {
        const float* krow = Kg + ((size_t)(b * S_ + cr) * NKV_ + kh) * HD_;
#pragma unroll
        for (int l = 0; l < 4; l++) {
            const int c = cb + l;
            cpa16(ksb[0] + crp * 256u + ((uint32_t)(c ^ kswz) << 4), krow + c * 4);
            cpa16(vtb[0] + cr * 256u + ((uint32_t)(c ^ vswz) << 4), vrow + c * 4);
        }
        cpa_commit();
    }

    // ---- load Q tile 128x64 (already tf32-rounded by ln_rope) ----
    {
        const int r = tid >> 1;
        const int hb = (tid & 1) * 8;
        const float* qp = Q + ((size_t)(b * S_ + qt * 128 + r) * NH_ + h) * HD_ + hb * 4;
#pragma unroll
        for (int l = 0; l < 8; l++) {
            float4 v = *(const float4*)(qp + l * 4);
            *(float4*)(Qs + r * 64 + (((hb + l) ^ (r & 7)) << 2)) = v;
        }
    }
    __syncthreads();

    // ---- hoist Q A-fragments (rows wm..wm+31, invariant across kt) ----
    unsigned qa[8][2][4];
#pragma unroll
    for (int ks = 0; ks < 8; ks++)
#pragma unroll
        for (int mt = 0; mt < 2; mt++) {
            const int sub = lane >> 3;
            const int row = wm + mt * 16 + (sub & 1) * 8 + (lane & 7);
            const int kc = 2 * ks + (sub >> 1);
            ldsm4(qa[ks][mt], qsb + (uint32_t)(row * 64 + ((kc ^ (row & 7)) << 2)) * 4u);
        }

    float acc_o[2][8][4];
#pragma unroll
    for (int mt = 0; mt < 2; mt++)
#pragma unroll
        for (int n8 = 0; n8 < 8; n8++)
#pragma unroll
            for (int e = 0; e < 4; e++) acc_o[mt][n8][e] = 0.0f;
    float m_[2][2] = { { -1e30f, -1e30f }, { -1e30f, -1e30f } };
    float l_[2][2] = { { 0.0f, 0.0f }, { 0.0f, 0.0f } };

    cpa_wait0();
    __syncthreads();   // KV tile 0 visible to all warps

    const int ktmax = 2 * qt + 1;
    for (int kt = 0; kt <= ktmax; kt++) {
        const int buf = kt & 1;

        // ---- S = Q @ K^T (warp: 32 rows x 32 keys) ----
        float sacc[2][4][4];
#pragma unroll
        for (int mt = 0; mt < 2; mt++)
#pragma unroll
            for (int nt = 0; nt < 4; nt++)
#pragma unroll
                for (int e = 0; e < 4; e++) sacc[mt][nt][e] = 0.0f;
#pragma unroll
        for (int ks = 0; ks < 8; ks++) {
#pragma unroll
            for (int bp = 0; bp < 2; bp++) {
                unsigned kbf[4];
                const int sub = lane >> 3;
                const int row = wn + bp * 16 + (sub >> 1) * 8 + (lane & 7);
                const int kc = 2 * ks + (sub & 1);
                ldsm4(kbf, ksb[buf] + (uint32_t)(row * 64 + ((kc ^ (row & 7)) << 2)) * 4u);
#pragma unroll
                for (int mt = 0; mt < 2; mt++) {
                    mma8(sacc[mt][bp * 2],     qa[ks][mt], kbf[0], kbf[1]);
                    mma8(sacc[mt][bp * 2 + 1], qa[ks][mt], kbf[2], kbf[3]);
                }
            }
        }

        // ---- causal mask (permuted cols: c0/c2 -> key t, c1/c3 -> key t+4) ----
        const int koff = kt * 64 - qt * 128;
        if (koff >= 0) {
#pragma unroll
            for (int mt = 0; mt < 2; mt++) {
                const int rA = wm + mt * 16 + (lane >> 2);
                const int rB = rA + 8;
#pragma unroll
                for (int nt = 0; nt < 4; nt++) {
                    const int k0 = koff + wn + nt * 8 + (lane & 3);
                    const int k1 = k0 + 4;
                    if (k0 > rA) sacc[mt][nt][0] = -1e30f;
                    if (k1 > rA) sacc[mt][nt][1] = -1e30f;
                    if (k0 > rB) sacc[mt][nt][2] = -1e30f;
                    if (k1 > rB) sacc[mt][nt][3] = -1e30f;
                }
            }
        }

        // ---- half-row max, publish ----
#pragma unroll
        for (int mt = 0; mt < 2; mt++) {
            float hmA = -1e30f, hmB = -1e30f;
#pragma unroll
            for (int nt = 0; nt < 4; nt++) {
                hmA = fmaxf(hmA, fmaxf(sacc[mt][nt][0], sacc[mt][nt][1]));
                hmB = fmaxf(hmB, fmaxf(sacc[mt][nt][2], sacc[mt][nt][3]));
            }
            hmA = fmaxf(hmA, __shfl_xor_sync(~0u, hmA, 1));
            hmA = fmaxf(hmA, __shfl_xor_sync(~0u, hmA, 2));
            hmB = fmaxf(hmB, __shfl_xor_sync(~0u, hmB, 1));
            hmB = fmaxf(hmB, __shfl_xor_sync(~0u, hmB, 2));
            if ((lane & 3) == 0) {
                mbuf[(wm + mt * 16 + (lane >> 2)) * 2 + wg] = hmA;
                mbuf[(wm + mt * 16 + 8 + (lane >> 2)) * 2 + wg] = hmB;
            }
        }
        __syncthreads();   // sync1 — also proves PV of kt-1 done by ALL warps

        // ---- issue cp.async for tile kt+1 into the buffer PV(kt-1) used ----
        if (kt < ktmax) {
            const int nb = buf ^ 1;
            const float* krow = Kg + ((size_t)(b * S_ + (kt + 1) * 64 + cr) * NKV_ + kh) * HD_;
            const float* vsrc = vrow + (kt + 1) * 64;
#pragma unroll
            for (int l = 0; l < 4; l++) {
                const int c = cb + l;
                cpa16(ksb[nb] + crp * 256u + ((uint32_t)(c ^ kswz) << 4), krow + c * 4);
                cpa16(vtb[nb] + cr * 256u + ((uint32_t)(c ^ vswz) << 4), vsrc + c * 4);
            }
            cpa_commit();
        }

        // ---- combine maxes, exp (in place -> tf32), half sums ----
        float alA[2], alB[2];
#pragma unroll
        for (int mt = 0; mt < 2; mt++) {
            const int rA = wm + mt * 16 + (lane >> 2);
            const int rB = rA + 8;
            const float mnA = fmaxf(m_[mt][0], fmaxf(mbuf[rA * 2], mbuf[rA * 2 + 1]));
            const float mnB = fmaxf(m_[mt][1], fmaxf(mbuf[rB * 2], mbuf[rB * 2 + 1]));
            alA[mt] = __expf(m_[mt][0] - mnA);
            alB[mt] = __expf(m_[mt][1] - mnB);
            m_[mt][0] = mnA; m_[mt][1] = mnB;
            float hsA = 0.0f, hsB = 0.0f;
#pragma unroll
            for (int nt = 0; nt < 4; nt++) {
                const float p0 = __expf(sacc[mt][nt][0] - mnA);
                const float p1 = __expf(sacc[mt][nt][1] - mnA);
                const float p2 = __expf(sacc[mt][nt][2] - mnB);
                const float p3 = __expf(sacc[mt][nt][3] - mnB);
                hsA += p0 + p1; hsB += p2 + p3;
                sacc[mt][nt][0] = __uint_as_float(tf32r(p0));
                sacc[mt][nt][1] = __uint_as_float(tf32r(p1));
                sacc[mt][nt][2] = __uint_as_float(tf32r(p2));
                sacc[mt][nt][3] = __uint_as_float(tf32r(p3));
            }
            hsA += __shfl_xor_sync(~0u, hsA, 1); hsA += __shfl_xor_sync(~0u, hsA, 2);
            hsB += __shfl_xor_sync(~0u, hsB, 1); hsB += __shfl_xor_sync(~0u, hsB, 2);
            if ((lane & 3) == 0) {
                sbuf[rA * 2 + wg] = hsA;
                sbuf[rB * 2 + wg] = hsB;
            }
        }
        // rescale O partials while sums publish
#pragma unroll
        for (int mt = 0; mt < 2; mt++)
#pragma unroll
            for (int n8 = 0; n8 < 8; n8++) {
                acc_o[mt][n8][0] *= alA[mt]; acc_o[mt][n8][1] *= alA[mt];
                acc_o[mt][n8][2] *= alB[mt]; acc_o[mt][n8][3] *= alB[mt];
            }
        __syncthreads();   // sync2
#pragma unroll
        for (int mt = 0; mt < 2; mt++) {
            const int rA = wm + mt * 16 + (lane >> 2);
            const int rB = rA + 8;
            l_[mt][0] = l_[mt][0] * alA[mt] + sbuf[rA * 2] + sbuf[rA * 2 + 1];
            l_[mt][1] = l_[mt][1] * alB[mt] + sbuf[rB * 2] + sbuf[rB * 2 + 1];
        }

        // ---- O += P @ V (P = sacc regs, reordered {c0,c2,c1,c3}) ----
#pragma unroll
        for (int ntb = 0; ntb < 4; ntb++) {
            const int kb8 = wg * 4 + ntb;
#pragma unroll
            for (int bp = 0; bp < 4; bp++) {
                unsigned vb[4];
                const int sub = lane >> 3;
                const int d = bp * 16 + (sub >> 1) * 8 + (lane & 7);
                const int jc = 2 * kb8 + (sub & 1);
                const int ch = jc ^ (d & 7) ^ ((d >> 4) & 3);
                ldsm4(vb, vtb[buf] + (uint32_t)(d * 64 + (ch << 2)) * 4u);
#pragma unroll
                for (int mt = 0; mt < 2; mt++) {
                    const unsigned* u = (const unsigned*)sacc[mt][ntb];
                    const unsigned pa[4] = { u[0], u[2], u[1], u[3] };
                    mma8(acc_o[mt][bp * 2],     pa, vb[0], vb[1]);
                    mma8(acc_o[mt][bp * 2 + 1], pa, vb[2], vb[3]);
                }
            }
        }

        cpa_wait0();
        __syncthreads();   // sync3 — next tile visible, PV done for all
    }

    // ---- epilogue: combine the two key-half partials, scale by 1/l ----
    if (wg == 1) {
#pragma unroll
        for (int mt = 0; mt < 2; mt++) {
            const int rA = wm + mt * 16 + (lane >> 2);
            const int rB = rA + 8;
#pragma unroll
            for (int n8 = 0; n8 < 8; n8++) {
                const int d0 = n8 * 8 + (lane & 3) * 2;
                *(float2*)(Ps + rA * 68 + d0) = make_float2(acc_o[mt][n8][0], acc_o[mt][n8][1]);
                *(float2*)(Ps + rB * 68 + d0) = make_float2(acc_o[mt][n8][2], acc_o[mt][n8][3]);
            }
        }
    }
    __syncthreads();
    if (wg == 0) {
#pragma unroll
        for (int mt = 0; mt < 2; mt++) {
            const int rA = wm + mt * 16 + (lane >> 2);
            const int rB = rA + 8;
            const float liA = 1.0f / l_[mt][0];
            const float liB = 1.0f / l_[mt][1];
            float* oA = O + (size_t)(b * S_ + qt * 128 + rA) * H_ + h * HD_;
            float* oB = O + (size_t)(b * S_ + qt * 128 + rB) * H_ + h * HD_;
#pragma unroll
            for (int n8 = 0; n8 < 8; n8++) {
                const int d0 = n8 * 8 + (lane & 3) * 2;
                const float2 pA = *(const float2*)(Ps + rA * 68 + d0);
                const float2 pB = *(const float2*)(Ps + rB * 68 + d0);
                *(float2*)(oA + d0) = make_float2((acc_o[mt][n8][0] + pA.x) * liA,
                                                  (acc_o[mt][n8][1] + pA.y) * liA);
                *(float2*)(oB + d0) = make_float2((acc_o[mt][n8][2] + pB.x) * liB,
                                                  (acc_o[mt][n8][3] + pB.y) * liB);
            }
        }
    }
}

// ---------------- launch ----------------
extern "C" void kernel_launch(void* const* d_in, const int* in_sizes, int n_in,
                              void* d_out, int out_size)
{
    const int*   pos  = (const int*)d_in[0];
    const float* hid  = (const float*)d_in[1];
    const float* wqkv = (const float*)d_in[2];
    const float* qw   = (const float*)d_in[3];
    const float* kw   = (const float*)d_in[4];
    const float* wo   = (const float*)d_in[5];
    float* out = (float*)d_out;

    float *qkv, *q, *k, *v, *attnb;
    cudaGetSymbolAddress((void**)&qkv,   g_qkv);
    cudaGetSymbolAddress((void**)&q,     g_q);
    cudaGetSymbolAddress((void**)&k,     g_k);
    cudaGetSymbolAddress((void**)&v,     g_v);
    cudaGetSymbolAddress((void**)&attnb, g_attn);

    cudaFuncSetAttribute(attn_mma3,
                         cudaFuncAttributeMaxDynamicSharedMemorySize, ATTN_SMEM_BYTES);

    // 1) qkv = hidden @ w_qkv^T
    dim3 g1(QKVN / 128, BS_ / 128);
    gemm_mma<<<g1, 256>>>(hid, wqkv, qkv, BS_, QKVN, H_);

    // 2a) per-head LN + partial RoPE (+ fold score scale into Q, tf32 round)
    ln_rope<<<BS_ * 5, 256>>>(qkv, pos, qw, kw, q, k);
    // 2b) transpose V to [b][kh][d][s] (tf32)
    prep_v<<<dim3(S_ / 64, B_ * NKV_), 256>>>(qkv, v);

    // 3) causal GQA attention (tf32 mma flash v3, cp.async double-buffered KV)
    attn_mma3<<<dim3(S_ / 128, B_ * NH_), 256, ATTN_SMEM_BYTES>>>(q, k, v, attnb);

    // 4) out = attn @ w_o^T
    dim3 g2(H_ / 128, BS_ / 128);
    gemm_mma<<<g2, 256>>>(attnb, wo, out, BS_, H_, H_);
}

// round 9
// speedup vs baseline: 3.0070x; 1.0179x over previous
#include <cuda_runtime.h>
#include <cstdint>
#include <cstddef>

// Problem constants (fixed by setup_inputs)
#define B_   2
#define S_   2048
#define H_   2048
#define NH_  32
#define NKV_ 8
#define HD_  64
#define QKVN 3072
#define BS_  (B_ * S_)   // 4096

// ---------------- scratch (device globals: allocation-free) ----------------
__device__ __align__(16) float g_qkv[(size_t)BS_ * QKVN];
__device__ __align__(16) float g_q[(size_t)BS_ * NH_ * HD_];
__device__ __align__(16) float g_k[(size_t)BS_ * NKV_ * HD_];
__device__ __align__(16) float g_v[(size_t)BS_ * NKV_ * HD_];   // [b][kh][d][s], tf32
__device__ __align__(16) float g_attn[(size_t)BS_ * NH_ * HD_];

// ---------------- helpers ----------------
__device__ __forceinline__ uint32_t smem_u32(const void* p) {
    uint32_t a;
    asm("{ .reg .u64 t; cvta.to.shared.u64 t, %1; cvt.u32.u64 %0, t; }" : "=r"(a) : "l"(p));
    return a;
}
__device__ __forceinline__ uint32_t tf32r(float f) {
    uint32_t r;
    asm("cvt.rna.tf32.f32 %0, %1;" : "=r"(r) : "f"(f));
    return r;
}
// m16n8k8 tf32 mma, fp32 accumulate (row.col)
__device__ __forceinline__ void mma8(float* d, const unsigned* a, unsigned b0, unsigned b1) {
    asm volatile(
        "mma.sync.aligned.m16n8k8.row.col.f32.tf32.tf32.f32 "
        "{%0,%1,%2,%3}, {%4,%5,%6,%7}, {%8,%9}, {%0,%1,%2,%3};"
        : "+f"(d[0]), "+f"(d[1]), "+f"(d[2]), "+f"(d[3])
        : "r"(a[0]), "r"(a[1]), "r"(a[2]), "r"(a[3]), "r"(b0), "r"(b1));
}
__device__ __forceinline__ void ldsm4(unsigned* r, uint32_t addr) {
    asm volatile("ldmatrix.sync.aligned.m8n8.x4.shared.b16 {%0,%1,%2,%3}, [%4];"
                 : "=r"(r[0]), "=r"(r[1]), "=r"(r[2]), "=r"(r[3]) : "r"(addr));
}
__device__ __forceinline__ void cvt4(unsigned* r) {
    r[0] = tf32r(__uint_as_float(r[0]));
    r[1] = tf32r(__uint_as_float(r[1]));
    r[2] = tf32r(__uint_as_float(r[2]));
    r[3] = tf32r(__uint_as_float(r[3]));
}
__device__ __forceinline__ void cpa16(uint32_t dst, const void* src) {
    asm volatile("cp.async.cg.shared.global [%0], [%1], 16;" :: "r"(dst), "l"(src) : "memory");
}
__device__ __forceinline__ void cpa_commit() {
    asm volatile("cp.async.commit_group;" ::: "memory");
}
__device__ __forceinline__ void cpa_wait0() {
    asm volatile("cp.async.wait_group 0;" ::: "memory");
}
__device__ __forceinline__ void cpa_wait1() {
    asm volatile("cp.async.wait_group 1;" ::: "memory");
}

// ======================= tf32 mma GEMM: C = A[M,K] @ W[N,K]^T ===============
// 128x128 tile, BK=16, 8 warps (2x4), 3-stage cp.async pipeline (raw f32 in
// smem; tf32 cvt applied to fragments in registers after ldmatrix).
// One __syncthreads per K16 tile.
__device__ __forceinline__ uint32_t gaddrA(uint32_t base, int m0, int ks, int lane) {
    int sub = lane >> 3;
    int row = m0 + (sub & 1) * 8 + (lane & 7);
    int kc  = 2 * ks + (sub >> 1);
    return base + (uint32_t)(row * 16 + ((kc ^ ((row >> 1) & 3)) << 2)) * 4u;
}
__device__ __forceinline__ uint32_t gaddrB(uint32_t base, int n0, int ks, int lane) {
    int sub = lane >> 3;
    int row = n0 + (sub >> 1) * 8 + (lane & 7);
    int kc  = 2 * ks + (sub & 1);
    return base + (uint32_t)(row * 16 + ((kc ^ ((row >> 1) & 3)) << 2)) * 4u;
}

__global__ __launch_bounds__(256) void gemm_mma(
    const float* __restrict__ A, const float* __restrict__ W,
    float* __restrict__ C, int M, int N, int K)
{
    __shared__ __align__(16) unsigned As[3][2048];   // 24 KB
    __shared__ __align__(16) unsigned Bs[3][2048];   // 24 KB
    const int tid = threadIdx.x, lane = tid & 31, wid = tid >> 5;
    const int bm = blockIdx.y * 128, bn = blockIdx.x * 128;
    const int wm = (wid & 1) * 64, wn = (wid >> 1) * 32;

    const int tr = tid >> 1;             // 0..127 (row within tile)
    const int tc = (tid & 1) * 2;        // 16B-chunk base (0 or 2)
    const float* Ap = A + (size_t)(bm + tr) * K + tc * 4;
    const float* Wp = W + (size_t)(bn + tr) * K + tc * 4;
    const uint32_t so0 = (uint32_t)(tr * 16 + (((tc    ) ^ ((tr >> 1) & 3)) << 2)) * 4u;
    const uint32_t so1 = (uint32_t)(tr * 16 + (((tc + 1) ^ ((tr >> 1) & 3)) << 2)) * 4u;

    const uint32_t asb[3] = { smem_u32(As[0]), smem_u32(As[1]), smem_u32(As[2]) };
    const uint32_t bsb[3] = { smem_u32(Bs[0]), smem_u32(Bs[1]), smem_u32(Bs[2]) };

    float acc[16][4];
#pragma unroll
    for (int i = 0; i < 16; i++)
#pragma unroll
        for (int j = 0; j < 4; j++) acc[i][j] = 0.0f;

    const int T = K >> 4;

    // ---- prologue: issue tiles 0 and 1 ----
#pragma unroll
    for (int s = 0; s < 2; s++) {
        const float* a = Ap + s * 16;
        const float* w = Wp + s * 16;
        cpa16(asb[s] + so0, a);     cpa16(asb[s] + so1, a + 4);
        cpa16(bsb[s] + so0, w);     cpa16(bsb[s] + so1, w + 4);
        cpa_commit();
    }

    for (int t = 0; t < T; t++) {
        cpa_wait1();        // tile t landed (≤1 group pending)
        __syncthreads();    // visible to all; all warps done reading buf (t-1)%3

        if (t + 2 < T) {    // refill buffer (t+2)%3 == (t-1)%3
            const int s = (t + 2) % 3;
            const float* a = Ap + (t + 2) * 16;
            const float* w = Wp + (t + 2) * 16;
            cpa16(asb[s] + so0, a);     cpa16(asb[s] + so1, a + 4);
            cpa16(bsb[s] + so0, w);     cpa16(bsb[s] + so1, w + 4);
            cpa_commit();
        }

        const int buf = t % 3;
#pragma unroll
        for (int ks = 0; ks < 2; ks++) {
            unsigned af[4][4], bf[2][4];
#pragma unroll
            for (int mt = 0; mt < 4; mt++) {
                ldsm4(af[mt], gaddrA(asb[buf], wm + mt * 16, ks, lane));
                cvt4(af[mt]);
            }
#pragma unroll
            for (int bp = 0; bp < 2; bp++) {
                ldsm4(bf[bp], gaddrB(bsb[buf], wn + bp * 16, ks, lane));
                cvt4(bf[bp]);
            }
#pragma unroll
            for (int mt = 0; mt < 4; mt++)
#pragma unroll
                for (int nt = 0; nt < 4; nt++)
                    mma8(acc[mt * 4 + nt], af[mt],
                         bf[nt >> 1][(nt & 1) * 2], bf[nt >> 1][(nt & 1) * 2 + 1]);
        }
    }

    // epilogue
#pragma unroll
    for (int mt = 0; mt < 4; mt++) {
        const int rA = bm + wm + mt * 16 + (lane >> 2);
        float* cA = C + (size_t)rA * N + bn + wn + (lane & 3) * 2;
        float* cB = cA + 8 * (size_t)N;
#pragma unroll
        for (int nt = 0; nt < 4; nt++) {
            *(float2*)(cA + nt * 8) = make_float2(acc[mt * 4 + nt][0], acc[mt * 4 + nt][1]);
            *(float2*)(cB + nt * 8) = make_float2(acc[mt * 4 + nt][2], acc[mt * 4 + nt][3]);
        }
    }
}

// ---------------- fused per-head LayerNorm + partial NeoX RoPE ----------------
__global__ __launch_bounds__(256) void ln_rope(
    const float* __restrict__ qkv, const int* __restrict__ pos_ids,
    const float* __restrict__ qw, const float* __restrict__ kw,
    float* __restrict__ qo, float* __restrict__ ko)
{
    const int wid = threadIdx.x >> 5;
    const int lane = threadIdx.x & 31;
    const int bs = blockIdx.x / 5;
    const int head = (blockIdx.x % 5) * 8 + wid;   // 0..39 (32 Q + 8 K)

    const float* src = qkv + (size_t)bs * QKVN + head * HD_;
    float v0 = src[lane], v1 = src[lane + 32];

    float s = v0 + v1;
#pragma unroll
    for (int m = 16; m; m >>= 1) s += __shfl_xor_sync(~0u, s, m);
    const float mu = s * (1.0f / 64.0f);
    const float d0 = v0 - mu, d1 = v1 - mu;
    float vs = d0 * d0 + d1 * d1;
#pragma unroll
    for (int m = 16; m; m >>= 1) vs += __shfl_xor_sync(~0u, vs, m);
    const float inv = rsqrtf(vs * (1.0f / 64.0f) + 1e-5f);

    const float* w = (head < NH_) ? (qw + head * HD_) : (kw + (head - NH_) * HD_);
    float n0 = d0 * inv * w[lane];
    float n1 = d1 * inv * w[lane + 32];

    const float p = (float)pos_ids[bs];
    const float partner = __shfl_xor_sync(~0u, n0, 8);
    if (lane < 16) {
        const int i = lane & 7;
        const float invf = powf(10000.0f, -(float)i * 0.125f);
        const float ang = p * invf;
        const float c = cosf(ang), sn = sinf(ang);
        n0 = (lane < 8) ? (n0 * c - partner * sn) : (n0 * c + partner * sn);
    }
    const float sc = (head < NH_) ? 0.125f : 1.0f;   // HEAD_DIM^-0.5 folded into Q
    n0 = __uint_as_float(tf32r(n0 * sc));
    n1 = __uint_as_float(tf32r(n1 * sc));

    if (head < NH_) {
        float* dst = qo + ((size_t)bs * NH_ + head) * HD_;
        dst[lane] = n0; dst[lane + 32] = n1;
    } else {
        float* dst = ko + ((size_t)bs * NKV_ + (head - NH_)) * HD_;
        dst[lane] = n0; dst[lane + 32] = n1;
    }
}

// ---------------- prep_v: transpose V to [b][kh][d][s] with tf32 round -------
__global__ __launch_bounds__(256) void prep_v(
    const float* __restrict__ qkv, float* __restrict__ V)
{
    __shared__ float ts[64][65];
    const int bkh = blockIdx.y;             // 0..15
    const int b = bkh >> 3, kh = bkh & 7;
    const int s0 = blockIdx.x * 64;
    const int r  = threadIdx.x >> 2;        // 0..63
    const int c0 = (threadIdx.x & 3) * 16;

    const float* src = qkv + (size_t)(b * S_ + s0 + r) * QKVN + 2560 + kh * 64 + c0;
#pragma unroll
    for (int l = 0; l < 4; l++) {
        float4 v = *(const float4*)(src + l * 4);
        ts[r][c0 + l * 4 + 0] = __uint_as_float(tf32r(v.x));
        ts[r][c0 + l * 4 + 1] = __uint_as_float(tf32r(v.y));
        ts[r][c0 + l * 4 + 2] = __uint_as_float(tf32r(v.z));
        ts[r][c0 + l * 4 + 3] = __uint_as_float(tf32r(v.w));
    }
    __syncthreads();

    const int d  = threadIdx.x >> 2;
    const int sc = (threadIdx.x & 3) * 16;
    float* dst = V + ((size_t)(b * NKV_ + kh) * HD_ + d) * S_ + s0 + sc;
#pragma unroll
    for (int l = 0; l < 4; l++) {
        float4 w = make_float4(ts[sc + l * 4 + 0][d], ts[sc + l * 4 + 1][d],
                               ts[sc + l * 4 + 2][d], ts[sc + l * 4 + 3][d]);
        *(float4*)(dst + l * 4) = w;
    }
}

// ======================= flash attention v3 (tf32 mma + cp.async) ============
// (unchanged from R8 — 128 q-rows/CTA, KV 64 tiles double-buffered cp.async,
//  permuted K rows so S accumulators feed PV directly)
// smem layout (bytes):
//   [0, 32768)          Qs [128][64]   (aliased as epilogue Ps, stride 68)
//   [32768, 49152)      Ks buf0        [49152, 65536)  Ks buf1
//   [65536, 81920)      Vt buf0        [81920, 98304)  Vt buf1
//   [98304, 99328)      mbuf [128][2]
//   [99328, 100352)     sbuf [128][2]
#define ATTN_SMEM_BYTES (98304 + 2048)

__global__ __launch_bounds__(256) void attn_mma3(
    const float* __restrict__ Q, const float* __restrict__ Kg,
    const float* __restrict__ Vg, float* __restrict__ O)
{
    extern __shared__ __align__(16) char smraw[];
    float* Qs = (float*)smraw;                              // [128][64] 32KB
    const uint32_t qsb = smem_u32(smraw);
    const uint32_t ksb[2] = { qsb + 32768u, qsb + 49152u }; // [64][64] x2
    const uint32_t vtb[2] = { qsb + 65536u, qsb + 81920u }; // [64][64] x2
    float* mbuf = (float*)(smraw + 98304);                  // [128][2] = 1KB
    float* sbuf = (float*)(smraw + 99328);                  // [128][2] = 1KB
    float* Ps   = (float*)smraw;                            // epilogue staging (stride 68)

    const int qt = (int)gridDim.x - 1 - (int)blockIdx.x;    // heavy tiles first
    const int bh = blockIdx.y;
    const int b = bh >> 5, h = bh & 31, kh = h >> 2;
    const int tid = threadIdx.x, lane = tid & 31, wid = tid >> 5;
    const int wm = (wid & 3) * 32;
    const int wg = wid >> 2;
    const int wn = wg * 32;

    // per-thread cp.async assignment: row cr (0..63), 16B chunks cb..cb+3 (0..15)
    const int cr = tid >> 2;
    const int cb = (tid & 3) * 4;
    const int crl = cr & 7;
    const int crp = (cr & 56) | ((crl & 3) * 2 + (crl >> 2));   // permuted K row
    const uint32_t kswz = (uint32_t)(crp & 7);
    const uint32_t vswz = (uint32_t)((cr & 7) ^ ((cr >> 4) & 3));
    const float* vrow = Vg + ((size_t)(b * NKV_ + kh) * HD_ + cr) * S_;

    // ---- issue KV tile 0 (overlaps the Q load) ----
    {
        const float* krow = Kg + ((size_t)(b * S_ + cr) * NKV_ + kh) * HD_;
#pragma unroll
        for (int l = 0; l < 4; l++) {
            const int c = cb + l;
            cpa16(ksb[0] + crp * 256u + ((uint32_t)(c ^ kswz) << 4), krow + c * 4);
            cpa16(vtb[0] + cr * 256u + ((uint32_t)(c ^ vswz) << 4), vrow + c * 4);
        }
        cpa_commit();
    }

    // ---- load Q tile 128x64 (already tf32-rounded by ln_rope) ----
    {
        const int r = tid >> 1;
        const int hb = (tid & 1) * 8;
        const float* qp = Q + ((size_t)(b * S_ + qt * 128 + r) * NH_ + h) * HD_ + hb * 4;
#pragma unroll
        for (int l = 0; l < 8; l++) {
            float4 v = *(const float4*)(qp + l * 4);
            *(float4*)(Qs + r * 64 + (((hb + l) ^ (r & 7)) << 2)) = v;
        }
    }
    __syncthreads();

    // ---- hoist Q A-fragments (rows wm..wm+31, invariant across kt) ----
    unsigned qa[8][2][4];
#pragma unroll
    for (int ks = 0; ks < 8; ks++)
#pragma unroll
        for (int mt = 0; mt < 2; mt++) {
            const int sub = lane >> 3;
            const int row = wm + mt * 16 + (sub & 1) * 8 + (lane & 7);
            const int kc = 2 * ks + (sub >> 1);
            ldsm4(qa[ks][mt], qsb + (uint32_t)(row * 64 + ((kc ^ (row & 7)) << 2)) * 4u);
        }

    float acc_o[2][8][4];
#pragma unroll
    for (int mt = 0; mt < 2; mt++)
#pragma unroll
        for (int n8 = 0; n8 < 8; n8++)
#pragma unroll
            for (int e = 0; e < 4; e++) acc_o[mt][n8][e] = 0.0f;
    float m_[2][2] = { { -1e30f, -1e30f }, { -1e30f, -1e30f } };
    float l_[2][2] = { { 0.0f, 0.0f }, { 0.0f, 0.0f } };

    cpa_wait0();
    __syncthreads();   // KV tile 0 visible to all warps

    const int ktmax = 2 * qt + 1;
    for (int kt = 0; kt <= ktmax; kt++) {
        const int buf = kt & 1;

        // ---- S = Q @ K^T (warp: 32 rows x 32 keys) ----
        float sacc[2][4][4];
#pragma unroll
        for (int mt = 0; mt < 2; mt++)
#pragma unroll
            for (int nt = 0; nt < 4; nt++)
#pragma unroll
                for (int e = 0; e < 4; e++) sacc[mt][nt][e] = 0.0f;
#pragma unroll
        for (int ks = 0; ks < 8; ks++) {
#pragma unroll
            for (int bp = 0; bp < 2; bp++) {
                unsigned kbf[4];
                const int sub = lane >> 3;
                const int row = wn + bp * 16 + (sub >> 1) * 8 + (lane & 7);
                const int kc = 2 * ks + (sub & 1);
                ldsm4(kbf, ksb[buf] + (uint32_t)(row * 64 + ((kc ^ (row & 7)) << 2)) * 4u);
#pragma unroll
                for (int mt = 0; mt < 2; mt++) {
                    mma8(sacc[mt][bp * 2],     qa[ks][mt], kbf[0], kbf[1]);
                    mma8(sacc[mt][bp * 2 + 1], qa[ks][mt], kbf[2], kbf[3]);
                }
            }
        }

        // ---- causal mask (permuted cols: c0/c2 -> key t, c1/c3 -> key t+4) ----
        const int koff = kt * 64 - qt * 128;
        if (koff >= 0) {
#pragma unroll
            for (int mt = 0; mt < 2; mt++) {
                const int rA = wm + mt * 16 + (lane >> 2);
                const int rB = rA + 8;
#pragma unroll
                for (int nt = 0; nt < 4; nt++) {
                    const int k0 = koff + wn + nt * 8 + (lane & 3);
                    const int k1 = k0 + 4;
                    if (k0 > rA) sacc[mt][nt][0] = -1e30f;
                    if (k1 > rA) sacc[mt][nt][1] = -1e30f;
                    if (k0 > rB) sacc[mt][nt][2] = -1e30f;
                    if (k1 > rB) sacc[mt][nt][3] = -1e30f;
                }
            }
        }

        // ---- half-row max, publish ----
#pragma unroll
        for (int mt = 0; mt < 2; mt++) {
            float hmA = -1e30f, hmB = -1e30f;
#pragma unroll
            for (int nt = 0; nt < 4; nt++) {
                hmA = fmaxf(hmA, fmaxf(sacc[mt][nt][0], sacc[mt][nt][1]));
                hmB = fmaxf(hmB, fmaxf(sacc[mt][nt][2], sacc[mt][nt][3]));
            }
            hmA = fmaxf(hmA, __shfl_xor_sync(~0u, hmA, 1));
            hmA = fmaxf(hmA, __shfl_xor_sync(~0u, hmA, 2));
            hmB = fmaxf(hmB, __shfl_xor_sync(~0u, hmB, 1));
            hmB = fmaxf(hmB, __shfl_xor_sync(~0u, hmB, 2));
            if ((lane & 3) == 0) {
                mbuf[(wm + mt * 16 + (lane >> 2)) * 2 + wg] = hmA;
                mbuf[(wm + mt * 16 + 8 + (lane >> 2)) * 2 + wg] = hmB;
            }
        }
        __syncthreads();   // sync1 — also proves PV of kt-1 done by ALL warps

        // ---- issue cp.async for tile kt+1 into the buffer PV(kt-1) used ----
        if (kt < ktmax) {
            const int nb = buf ^ 1;
            const float* krow = Kg + ((size_t)(b * S_ + (kt + 1) * 64 + cr) * NKV_ + kh) * HD_;
            const float* vsrc = vrow + (kt + 1) * 64;
#pragma unroll
            for (int l = 0; l < 4; l++) {
                const int c = cb + l;
                cpa16(ksb[nb] + crp * 256u + ((uint32_t)(c ^ kswz) << 4), krow + c * 4);
                cpa16(vtb[nb] + cr * 256u + ((uint32_t)(c ^ vswz) << 4), vsrc + c * 4);
            }
            cpa_commit();
        }

        // ---- combine maxes, exp (in place -> tf32), half sums ----
        float alA[2], alB[2];
#pragma unroll
        for (int mt = 0; mt < 2; mt++) {
            const int rA = wm + mt * 16 + (lane >> 2);
            const int rB = rA + 8;
            const float mnA = fmaxf(m_[mt][0], fmaxf(mbuf[rA * 2], mbuf[rA * 2 + 1]));
            const float mnB = fmaxf(m_[mt][1], fmaxf(mbuf[rB * 2], mbuf[rB * 2 + 1]));
            alA[mt] = __expf(m_[mt][0] - mnA);
            alB[mt] = __expf(m_[mt][1] - mnB);
            m_[mt][0] = mnA; m_[mt][1] = mnB;
            float hsA = 0.0f, hsB = 0.0f;
#pragma unroll
            for (int nt = 0; nt < 4; nt++) {
                const float p0 = __expf(sacc[mt][nt][0] - mnA);
                const float p1 = __expf(sacc[mt][nt][1] - mnA);
                const float p2 = __expf(sacc[mt][nt][2] - mnB);
                const float p3 = __expf(sacc[mt][nt][3] - mnB);
                hsA += p0 + p1; hsB += p2 + p3;
                sacc[mt][nt][0] = __uint_as_float(tf32r(p0));
                sacc[mt][nt][1] = __uint_as_float(tf32r(p1));
                sacc[mt][nt][2] = __uint_as_float(tf32r(p2));
                sacc[mt][nt][3] = __uint_as_float(tf32r(p3));
            }
            hsA += __shfl_xor_sync(~0u, hsA, 1); hsA += __shfl_xor_sync(~0u, hsA, 2);
            hsB += __shfl_xor_sync(~0u, hsB, 1); hsB += __shfl_xor_sync(~0u, hsB, 2);
            if ((lane & 3) == 0) {
                sbuf[rA * 2 + wg] = hsA;
                sbuf[rB * 2 + wg] = hsB;
            }
        }
        // rescale O partials while sums publish
#pragma unroll
        for (int mt = 0; mt < 2; mt++)
#pragma unroll
            for (int n8 = 0; n8 < 8; n8++) {
                acc_o[mt][n8][0] *= alA[mt]; acc_o[mt][n8][1] *= alA[mt];
                acc_o[mt][n8][2] *= alB[mt]; acc_o[mt][n8][3] *= alB[mt];
            }
        __syncthreads();   // sync2
#pragma unroll
        for (int mt = 0; mt < 2; mt++) {
            const int rA = wm + mt * 16 + (lane >> 2);
            const int rB = rA + 8;
            l_[mt][0] = l_[mt][0] * alA[mt] + sbuf[rA * 2] + sbuf[rA * 2 + 1];
            l_[mt][1] = l_[mt][1] * alB[mt] + sbuf[rB * 2] + sbuf[rB * 2 + 1];
        }

        // ---- O += P @ V (P = sacc regs, reordered {c0,c2,c1,c3}) ----
#pragma unroll
        for (int ntb = 0; ntb < 4; ntb++) {
            const int kb8 = wg * 4 + ntb;
#pragma unroll
            for (int bp = 0; bp < 4; bp++) {
                unsigned vb[4];
                const int sub = lane >> 3;
                const int d = bp * 16 + (sub >> 1) * 8 + (lane & 7);
                const int jc = 2 * kb8 + (sub & 1);
                const int ch = jc ^ (d & 7) ^ ((d >> 4) & 3);
                ldsm4(vb, vtb[buf] + (uint32_t)(d * 64 + (ch << 2)) * 4u);
#pragma unroll
                for (int mt = 0; mt < 2; mt++) {
                    const unsigned* u = (const unsigned*)sacc[mt][ntb];
                    const unsigned pa[4] = { u[0], u[2], u[1], u[3] };
                    mma8(acc_o[mt][bp * 2],     pa, vb[0], vb[1]);
                    mma8(acc_o[mt][bp * 2 + 1], pa, vb[2], vb[3]);
                }
            }
        }

        cpa_wait0();
        __syncthreads();   // sync3 — next tile visible, PV done for all
    }

    // ---- epilogue: combine the two key-half partials, scale by 1/l ----
    if (wg == 1) {
#pragma unroll
        for (int mt = 0; mt < 2; mt++) {
            const int rA = wm + mt * 16 + (lane >> 2);
            const int rB = rA + 8;
#pragma unroll
            for (int n8 = 0; n8 < 8; n8++) {
                const int d0 = n8 * 8 + (lane & 3) * 2;
                *(float2*)(Ps + rA * 68 + d0) = make_float2(acc_o[mt][n8][0], acc_o[mt][n8][1]);
                *(float2*)(Ps + rB * 68 + d0) = make_float2(acc_o[mt][n8][2], acc_o[mt][n8][3]);
            }
        }
    }
    __syncthreads();
    if (wg == 0) {
#pragma unroll
        for (int mt = 0; mt < 2; mt++) {
            const int rA = wm + mt * 16 + (lane >> 2);
            const int rB = rA + 8;
            const float liA = 1.0f / l_[mt][0];
            const float liB = 1.0f / l_[mt][1];
            float* oA = O + (size_t)(b * S_ + qt * 128 + rA) * H_ + h * HD_;
            float* oB = O + (size_t)(b * S_ + qt * 128 + rB) * H_ + h * HD_;
#pragma unroll
            for (int n8 = 0; n8 < 8; n8++) {
                const int d0 = n8 * 8 + (lane & 3) * 2;
                const float2 pA = *(const float2*)(Ps + rA * 68 + d0);
                const float2 pB = *(const float2*)(Ps + rB * 68 + d0);
                *(float2*)(oA + d0) = make_float2((acc_o[mt][n8][0] + pA.x) * liA,
                                                  (acc_o[mt][n8][1] + pA.y) * liA);
                *(float2*)(oB + d0) = make_float2((acc_o[mt][n8][2] + pB.x) * liB,
                                                  (acc_o[mt][n8][3] + pB.y) * liB);
            }
        }
    }
}

// ---------------- launch ----------------
extern "C" void kernel_launch(void* const* d_in, const int* in_sizes, int n_in,
                              void* d_out, int out_size)
{
    const int*   pos  = (const int*)d_in[0];
    const float* hid  = (const float*)d_in[1];
    const float* wqkv = (const float*)d_in[2];
    const float* qw   = (const float*)d_in[3];
    const float* kw   = (const float*)d_in[4];
    const float* wo   = (const float*)d_in[5];
    float* out = (float*)d_out;

    float *qkv, *q, *k, *v, *attnb;
    cudaGetSymbolAddress((void**)&qkv,   g_qkv);
    cudaGetSymbolAddress((void**)&q,     g_q);
    cudaGetSymbolAddress((void**)&k,     g_k);
    cudaGetSymbolAddress((void**)&v,     g_v);
    cudaGetSymbolAddress((void**)&attnb, g_attn);

    cudaFuncSetAttribute(attn_mma3,
                         cudaFuncAttributeMaxDynamicSharedMemorySize, ATTN_SMEM_BYTES);

    // 1) qkv = hidden @ w_qkv^T
    dim3 g1(QKVN / 128, BS_ / 128);
    gemm_mma<<<g1, 256>>>(hid, wqkv, qkv, BS_, QKVN, H_);

    // 2a) per-head LN + partial RoPE (+ fold score scale into Q, tf32 round)
    ln_rope<<<BS_ * 5, 256>>>(qkv, pos, qw, kw, q, k);
    // 2b) transpose V to [b][kh][d][s] (tf32)
    prep_v<<<dim3(S_ / 64, B_ * NKV_), 256>>>(qkv, v);

    // 3) causal GQA attention (tf32 mma flash v3, cp.async double-buffered KV)
    attn_mma3<<<dim3(S_ / 128, B_ * NH_), 256, ATTN_SMEM_BYTES>>>(q, k, v, attnb);

    // 4) out = attn @ w_o^T
    dim3 g2(H_ / 128, BS_ / 128);
    gemm_mma<<<g2, 256>>>(attnb, wo, out, BS_, H_, H_);
}